// round 2
// baseline (speedup 1.0000x reference)
#include <cuda_runtime.h>
#include <math.h>

#define BB 2
#define TT 2048
#define EE 2048
#define HH 16
#define HKV 8
#define DD 128

// ---------------- scratch (static device globals; no allocation) ----------------
__device__ float g_qlin[BB*TT*HH*DD];     // [B,T,H*D]   x@wq
__device__ float g_klin[BB*TT*HKV*DD];    // [B,T,HKV*D] x@wk
__device__ float g_vlin[BB*TT*HKV*DD];    // [B,T,HKV*D] x@wv
__device__ float g_q[BB*HH*TT*DD];        // [B,H,T,D]   rope(q)
__device__ float g_k[BB*HKV*TT*DD];       // [B,HKV,T,D] rope(k)
__device__ float g_v[BB*HKV*TT*DD];       // [B,HKV,T,D] v transposed
__device__ float g_attn[BB*TT*HH*DD];     // [B,T,H*D]   attention output

// ---------------- SGEMM: C[M,N] = A[M,K] @ B[K,N], all row-major ----------------
// 128x128 block tile, BK=16, 256 threads, 8x8 register tile (strided by 16).
__global__ void sgemm_kernel(const float* __restrict__ A, const float* __restrict__ Bm,
                             float* __restrict__ C, int M, int N, int K) {
    __shared__ float As[16][128];
    __shared__ float Bs[16][132];

    const int tid  = threadIdx.x;
    const int brow = blockIdx.y * 128;
    const int bcol = blockIdx.x * 128;
    const int ty = tid >> 4;       // 0..15
    const int tx = tid & 15;       // 0..15

    float acc[8][8];
#pragma unroll
    for (int i = 0; i < 8; i++)
#pragma unroll
        for (int j = 0; j < 8; j++) acc[i][j] = 0.f;

    const int arow = tid >> 2;          // 0..63
    const int acol = (tid & 3) << 2;    // 0,4,8,12
    const int brw  = tid >> 5;          // 0..7
    const int bcl  = (tid & 31) << 2;   // 0..124

    for (int k0 = 0; k0 < K; k0 += 16) {
#pragma unroll
        for (int i = 0; i < 2; i++) {
            float4 a = *(const float4*)(A + (size_t)(brow + arow + i*64) * K + k0 + acol);
            As[acol+0][arow + i*64] = a.x;
            As[acol+1][arow + i*64] = a.y;
            As[acol+2][arow + i*64] = a.z;
            As[acol+3][arow + i*64] = a.w;
        }
#pragma unroll
        for (int i = 0; i < 2; i++) {
            float4 b = *(const float4*)(Bm + (size_t)(k0 + brw + i*8) * N + bcol + bcl);
            *(float4*)&Bs[brw + i*8][bcl] = b;
        }
        __syncthreads();
#pragma unroll
        for (int kk = 0; kk < 16; kk++) {
            float af[8], bf[8];
#pragma unroll
            for (int i = 0; i < 8; i++) af[i] = As[kk][ty + 16*i];
#pragma unroll
            for (int j = 0; j < 8; j++) bf[j] = Bs[kk][tx + 16*j];
#pragma unroll
            for (int i = 0; i < 8; i++)
#pragma unroll
                for (int j = 0; j < 8; j++)
                    acc[i][j] += af[i] * bf[j];
        }
        __syncthreads();
    }

#pragma unroll
    for (int i = 0; i < 8; i++)
#pragma unroll
        for (int j = 0; j < 8; j++)
            C[(size_t)(brow + ty + 16*i) * N + bcol + tx + 16*j] = acc[i][j];
}

// ---------------- RoPE + [B,T,Hx,D] -> [B,Hx,T,D] ----------------
__global__ void rope_kernel(const float* __restrict__ lin, float* __restrict__ out, int Hx) {
    int idx = blockIdx.x * blockDim.x + threadIdx.x;
    int total = BB * TT * Hx * (DD / 2);
    if (idx >= total) return;
    int j = idx & 63;
    int h = (idx >> 6) % Hx;
    int t = (idx / (64 * Hx)) % TT;
    int b = idx / (64 * Hx * TT);

    float inv = 1.0f / powf(10000.0f, (float)j * (1.0f / 64.0f));
    float ang = (float)t * inv;
    float s, c;
    sincosf(ang, &s, &c);

    const float* p = lin + (((size_t)b * TT + t) * Hx + h) * DD;
    float q1 = p[2*j];
    float q2 = p[2*j + 1];
    float* o = out + (((size_t)b * Hx + h) * TT + t) * DD;
    o[j]      = q1 * c - q2 * s;
    o[j + 64] = q2 * c + q1 * s;
}

// ---------------- V: [B,T,HKV,D] -> [B,HKV,T,D] ----------------
__global__ void vtrans_kernel(const float* __restrict__ lin, float* __restrict__ out) {
    int idx = blockIdx.x * blockDim.x + threadIdx.x;
    int total = BB * TT * HKV * DD;
    if (idx >= total) return;
    int d = idx & 127;
    int h = (idx >> 7) & 7;
    int t = (idx >> 10) % TT;
    int b = idx / (1024 * TT);
    out[(((size_t)b * HKV + h) * TT + t) * DD + d] = lin[idx];
}

// ---------------- Flash attention (fp32, causal) ----------------
// grid: (T/64, H, B); block: 256 threads.
// Q tile 64x128, KV tiles 64x128, S 64x64 in smem, O in registers.
__global__ void flash_kernel(const float* __restrict__ Qg_, const float* __restrict__ Kg_,
                             const float* __restrict__ Vg_, float* __restrict__ Og) {
    extern __shared__ float sm[];
    float* Qs = sm;                 // 64*132
    float* Ks = sm + 64 * 132;      // 64*132
    float* Vs = sm + 2 * 64 * 132;  // 64*132
    float* Ss = sm + 3 * 64 * 132;  // 64*65

    const int tid = threadIdx.x;
    const int qt  = blockIdx.x;     // q tile
    const int h   = blockIdx.y;
    const int b   = blockIdx.z;
    const int q0  = qt * 64;
    // NOTE: reference uses jnp.tile along head axis -> q head h attends kv head (h % HKV)
    const int hkv = h & (HKV - 1);
    const float scale = 0.08838834764831845f;   // 1/sqrt(128)

    const float* Qg = Qg_ + (((size_t)b * HH  + h  ) * TT + q0) * DD;
    const float* Kg = Kg_ + (((size_t)b * HKV + hkv) * TT     ) * DD;
    const float* Vg = Vg_ + (((size_t)b * HKV + hkv) * TT     ) * DD;

    // load Q tile (8192 floats, padded rows of 132)
#pragma unroll
    for (int it = 0; it < 8; it++) {
        int idx = tid + it * 256;       // float4 index 0..2047
        int row = idx >> 5;
        int col = (idx & 31) << 2;
        *(float4*)(Qs + row * 132 + col) = *(const float4*)(Qg + (size_t)idx * 4);
    }

    const int ty = tid >> 4, tx = tid & 15;   // S-compute mapping
    const int r  = tid >> 2, g  = tid & 3;    // softmax / PV mapping

    float m_r = -INFINITY, l_r = 0.f;
    float Oacc[32];
#pragma unroll
    for (int j = 0; j < 32; j++) Oacc[j] = 0.f;

    for (int kt = 0; kt <= qt; kt++) {
        __syncthreads();   // prev PV done with Ss/Vs (and Q store->read on iter 0)

        const float* kg = Kg + (size_t)kt * 64 * DD;
        const float* vg = Vg + (size_t)kt * 64 * DD;
#pragma unroll
        for (int it = 0; it < 8; it++) {
            int idx = tid + it * 256;
            int row = idx >> 5;
            int col = (idx & 31) << 2;
            *(float4*)(Ks + row * 132 + col) = *(const float4*)(kg + (size_t)idx * 4);
            *(float4*)(Vs + row * 132 + col) = *(const float4*)(vg + (size_t)idx * 4);
        }
        __syncthreads();

        // S = Q @ K^T  (each thread: rows {ty+16i}, cols {tx+16j})
        float acc[4][4];
#pragma unroll
        for (int i = 0; i < 4; i++)
#pragma unroll
            for (int j = 0; j < 4; j++) acc[i][j] = 0.f;

#pragma unroll 4
        for (int k4 = 0; k4 < 32; k4++) {
            float4 af[4], bf[4];
#pragma unroll
            for (int i = 0; i < 4; i++) af[i] = *(const float4*)(Qs + (ty + 16*i) * 132 + k4 * 4);
#pragma unroll
            for (int j = 0; j < 4; j++) bf[j] = *(const float4*)(Ks + (tx + 16*j) * 132 + k4 * 4);
#pragma unroll
            for (int i = 0; i < 4; i++)
#pragma unroll
                for (int j = 0; j < 4; j++) {
                    acc[i][j] += af[i].x * bf[j].x;
                    acc[i][j] += af[i].y * bf[j].y;
                    acc[i][j] += af[i].z * bf[j].z;
                    acc[i][j] += af[i].w * bf[j].w;
                }
        }

        const bool diag = (kt == qt);
#pragma unroll
        for (int i = 0; i < 4; i++)
#pragma unroll
            for (int j = 0; j < 4; j++) {
                int rr = ty + 16*i, cc = tx + 16*j;
                float v = acc[i][j] * scale;
                if (diag && cc > rr) v = -INFINITY;
                Ss[rr * 65 + cc] = v;
            }
        __syncthreads();

        // online softmax: 4 threads per row (lanes tid&3 within same warp)
        float mx = m_r;
#pragma unroll
        for (int c = 0; c < 16; c++) mx = fmaxf(mx, Ss[r * 65 + g * 16 + c]);
        mx = fmaxf(mx, __shfl_xor_sync(0xffffffffu, mx, 1));
        mx = fmaxf(mx, __shfl_xor_sync(0xffffffffu, mx, 2));

        float corr = expf(m_r - mx);   // m_r=-inf first tile -> 0
        float psum = 0.f;
#pragma unroll
        for (int c = 0; c < 16; c++) {
            float p = expf(Ss[r * 65 + g * 16 + c] - mx);
            Ss[r * 65 + g * 16 + c] = p;
            psum += p;
        }
        psum += __shfl_xor_sync(0xffffffffu, psum, 1);
        psum += __shfl_xor_sync(0xffffffffu, psum, 2);
        l_r = l_r * corr + psum;
        m_r = mx;
#pragma unroll
        for (int j = 0; j < 32; j++) Oacc[j] *= corr;
        __syncthreads();

        // O += P @ V  (thread: row r, d-cols g*32..g*32+31)
        for (int s = 0; s < 64; s++) {
            float p = Ss[r * 65 + s];
            const float4* vrow = (const float4*)(Vs + s * 132 + g * 32);
#pragma unroll
            for (int jj = 0; jj < 8; jj++) {
                float4 v = vrow[jj];
                Oacc[jj*4 + 0] += p * v.x;
                Oacc[jj*4 + 1] += p * v.y;
                Oacc[jj*4 + 2] += p * v.z;
                Oacc[jj*4 + 3] += p * v.w;
            }
        }
    }

    float invl = 1.0f / l_r;
    float* outp = Og + (((size_t)b * TT + q0 + r) * HH + h) * DD + g * 32;
#pragma unroll
    for (int jj = 0; jj < 8; jj++) {
        float4 v;
        v.x = Oacc[jj*4 + 0] * invl;
        v.y = Oacc[jj*4 + 1] * invl;
        v.z = Oacc[jj*4 + 2] * invl;
        v.w = Oacc[jj*4 + 3] * invl;
        *(float4*)(outp + jj * 4) = v;
    }
}

// ---------------- launch ----------------
extern "C" void kernel_launch(void* const* d_in, const int* in_sizes, int n_in,
                              void* d_out, int out_size) {
    const float* x  = (const float*)d_in[0];
    // d_in[1] = mask (tril, implicit in flash kernel)
    const float* wq = (const float*)d_in[2];
    const float* wk = (const float*)d_in[3];
    const float* wv = (const float*)d_in[4];
    const float* wo = (const float*)d_in[5];
    float* out = (float*)d_out;

    float *qlin, *klin, *vlin, *q, *k, *v, *attn;
    cudaGetSymbolAddress((void**)&qlin, g_qlin);
    cudaGetSymbolAddress((void**)&klin, g_klin);
    cudaGetSymbolAddress((void**)&vlin, g_vlin);
    cudaGetSymbolAddress((void**)&q,    g_q);
    cudaGetSymbolAddress((void**)&k,    g_k);
    cudaGetSymbolAddress((void**)&v,    g_v);
    cudaGetSymbolAddress((void**)&attn, g_attn);

    const int M = BB * TT;    // 4096

    // QKV projections
    sgemm_kernel<<<dim3(HH*DD/128,  M/128), 256>>>(x, wq, qlin, M, HH*DD,  EE);
    sgemm_kernel<<<dim3(HKV*DD/128, M/128), 256>>>(x, wk, klin, M, HKV*DD, EE);
    sgemm_kernel<<<dim3(HKV*DD/128, M/128), 256>>>(x, wv, vlin, M, HKV*DD, EE);

    // RoPE + layout transforms
    {
        int tq = BB * TT * HH  * (DD/2);
        int tk = BB * TT * HKV * (DD/2);
        int tv = BB * TT * HKV * DD;
        rope_kernel<<<(tq + 255)/256, 256>>>(qlin, q, HH);
        rope_kernel<<<(tk + 255)/256, 256>>>(klin, k, HKV);
        vtrans_kernel<<<(tv + 255)/256, 256>>>(vlin, v);
    }

    // Flash attention
    {
        size_t smem = (3 * 64 * 132 + 64 * 65) * sizeof(float);  // 118016 B
        cudaFuncSetAttribute(flash_kernel, cudaFuncAttributeMaxDynamicSharedMemorySize, (int)smem);
        flash_kernel<<<dim3(TT/64, HH, BB), 256, smem>>>(q, k, v, attn);
    }

    // Output projection
    sgemm_kernel<<<dim3(EE/128, M/128), 256>>>(attn, wo, out, M, EE, EE);
}

// round 3
// speedup vs baseline: 3.7731x; 3.7731x over previous
#include <cuda_runtime.h>
#include <math.h>
#include <stdint.h>

#define BB 2
#define TT 2048
#define EE 2048
#define HH 16
#define HKV 8
#define DD 128

// ---------------- scratch (static device globals; no allocation) ----------------
__device__ float g_qlin[BB*TT*HH*DD];     // [B,T,H*D]   x@wq
__device__ float g_klin[BB*TT*HKV*DD];    // [B,T,HKV*D] x@wk
__device__ float g_vlin[BB*TT*HKV*DD];    // [B,T,HKV*D] x@wv
__device__ float g_q[BB*HH*TT*DD];        // [B,H,T,D]   rope(q)
__device__ float g_k[BB*HKV*TT*DD];       // [B,HKV,T,D] rope(k)
__device__ float g_v[BB*HKV*TT*DD];       // [B,HKV,T,D] v transposed
__device__ float g_attn[BB*TT*HH*DD];     // [B,T,H*D]   attention output

__device__ __forceinline__ uint32_t f2tf(float x) {
    uint32_t u;
    asm("cvt.rna.tf32.f32 %0, %1;" : "=r"(u) : "f"(x));
    return u;
}

__device__ __forceinline__ void mma_tf32(float* d, const uint32_t* a, const uint32_t* b) {
    asm volatile(
        "mma.sync.aligned.m16n8k8.row.col.f32.tf32.tf32.f32 "
        "{%0,%1,%2,%3}, {%4,%5,%6,%7}, {%8,%9}, {%0,%1,%2,%3};"
        : "+f"(d[0]), "+f"(d[1]), "+f"(d[2]), "+f"(d[3])
        : "r"(a[0]), "r"(a[1]), "r"(a[2]), "r"(a[3]), "r"(b[0]), "r"(b[1]));
}

// ---------------- tf32 tensor-core GEMM: C[M,N] = A[M,K] @ B[K,N] row-major ----
// 128x128 block tile, BK=32, 256 threads (8 warps in 2x4), warp tile 64x32.
__global__ void tf32gemm_kernel(const float* __restrict__ A, const float* __restrict__ Bm,
                                float* __restrict__ C, int M, int N, int K) {
    __shared__ uint32_t As[32][136];   // [k][m], tf32 bits
    __shared__ uint32_t Bs[32][136];   // [k][n], tf32 bits

    const int tid  = threadIdx.x;
    const int brow = blockIdx.y * 128;
    const int bcol = blockIdx.x * 128;
    const int lane = tid & 31, warp = tid >> 5;
    const int wr = warp >> 2, wc = warp & 3;          // 2 x 4 warp grid
    const int m_base = wr * 64, n_base = wc * 32;
    const int lr = lane >> 2, lc = lane & 3;

    float acc[4][4][4];
#pragma unroll
    for (int mt = 0; mt < 4; mt++)
#pragma unroll
        for (int nt = 0; nt < 4; nt++)
#pragma unroll
            for (int i = 0; i < 4; i++) acc[mt][nt][i] = 0.f;

    const int arow = tid >> 1;            // 0..127
    const int ak0  = (tid & 1) * 16;      // 0 / 16
    const int bkr  = tid >> 3;            // 0..31
    const int bn0  = (tid & 7) * 4;       // 0..28

    for (int k0 = 0; k0 < K; k0 += 32) {
        // load A tile (transposed into [k][m])
#pragma unroll
        for (int i = 0; i < 4; i++) {
            float4 a = *(const float4*)(A + (size_t)(brow + arow) * K + k0 + ak0 + i * 4);
            int kk = ak0 + i * 4;
            As[kk + 0][arow] = f2tf(a.x);
            As[kk + 1][arow] = f2tf(a.y);
            As[kk + 2][arow] = f2tf(a.z);
            As[kk + 3][arow] = f2tf(a.w);
        }
        // load B tile ([k][n])
#pragma unroll
        for (int i = 0; i < 4; i++) {
            float4 b = *(const float4*)(Bm + (size_t)(k0 + bkr) * N + bcol + bn0 + i * 32);
            uint32_t* p = &Bs[bkr][bn0 + i * 32];
            p[0] = f2tf(b.x); p[1] = f2tf(b.y); p[2] = f2tf(b.z); p[3] = f2tf(b.w);
        }
        __syncthreads();

#pragma unroll
        for (int ks = 0; ks < 4; ks++) {
            const int kk = ks * 8;
            uint32_t afr[4][4], bfr[4][2];
#pragma unroll
            for (int mt = 0; mt < 4; mt++) {
                int m0 = m_base + mt * 16;
                afr[mt][0] = As[kk + lc][m0 + lr];
                afr[mt][1] = As[kk + lc][m0 + lr + 8];
                afr[mt][2] = As[kk + 4 + lc][m0 + lr];
                afr[mt][3] = As[kk + 4 + lc][m0 + lr + 8];
            }
#pragma unroll
            for (int nt = 0; nt < 4; nt++) {
                int n0 = n_base + nt * 8;
                bfr[nt][0] = Bs[kk + lc][n0 + lr];
                bfr[nt][1] = Bs[kk + 4 + lc][n0 + lr];
            }
#pragma unroll
            for (int mt = 0; mt < 4; mt++)
#pragma unroll
                for (int nt = 0; nt < 4; nt++)
                    mma_tf32(acc[mt][nt], afr[mt], bfr[nt]);
        }
        __syncthreads();
    }

#pragma unroll
    for (int mt = 0; mt < 4; mt++)
#pragma unroll
        for (int nt = 0; nt < 4; nt++) {
            int row = brow + m_base + mt * 16 + lr;
            int col = bcol + n_base + nt * 8 + lc * 2;
            *(float2*)(C + (size_t)row * N + col)       = make_float2(acc[mt][nt][0], acc[mt][nt][1]);
            *(float2*)(C + (size_t)(row + 8) * N + col) = make_float2(acc[mt][nt][2], acc[mt][nt][3]);
        }
}

// ---------------- RoPE + [B,T,Hx,D] -> [B,Hx,T,D] ----------------
__global__ void rope_kernel(const float* __restrict__ lin, float* __restrict__ out, int Hx) {
    int idx = blockIdx.x * blockDim.x + threadIdx.x;
    int total = BB * TT * Hx * (DD / 2);
    if (idx >= total) return;
    int j = idx & 63;
    int h = (idx >> 6) % Hx;
    int t = (idx / (64 * Hx)) % TT;
    int b = idx / (64 * Hx * TT);

    float inv = 1.0f / powf(10000.0f, (float)j * (1.0f / 64.0f));
    float ang = (float)t * inv;
    float s, c;
    sincosf(ang, &s, &c);

    const float* p = lin + (((size_t)b * TT + t) * Hx + h) * DD;
    float q1 = p[2*j];
    float q2 = p[2*j + 1];
    float* o = out + (((size_t)b * Hx + h) * TT + t) * DD;
    o[j]      = q1 * c - q2 * s;
    o[j + 64] = q2 * c + q1 * s;
}

// ---------------- V: [B,T,HKV,D] -> [B,HKV,T,D] ----------------
__global__ void vtrans_kernel(const float* __restrict__ lin, float* __restrict__ out) {
    int idx = blockIdx.x * blockDim.x + threadIdx.x;
    int total = BB * TT * HKV * DD;
    if (idx >= total) return;
    int d = idx & 127;
    int h = (idx >> 7) & 7;
    int t = (idx >> 10) % TT;
    int b = idx / (1024 * TT);
    out[(((size_t)b * HKV + h) * TT + t) * DD + d] = lin[idx];
}

// ---------------- Flash attention (fp32, causal) ----------------
// grid: (T/64, H, B); block: 256 threads.
__global__ void flash_kernel(const float* __restrict__ Qg_, const float* __restrict__ Kg_,
                             const float* __restrict__ Vg_, float* __restrict__ Og) {
    extern __shared__ float sm[];
    float* Qs = sm;                  // 64*132
    float* Ks = sm + 8448;           // 64*132
    float* Vs = sm + 16896;          // 64*132
    float* Ss = sm + 25344;          // 64*65
    float* m_s    = sm + 29504;      // 64
    float* l_s    = sm + 29568;      // 64
    float* corr_s = sm + 29632;      // 64

    const int tid = threadIdx.x;
    const int qt  = blockIdx.x;
    const int h   = blockIdx.y;
    const int b   = blockIdx.z;
    const int q0  = qt * 64;
    const int hkv = h & (HKV - 1);   // jnp.tile mapping: kv head = h % HKV
    const float scale = 0.08838834764831845f;   // 1/sqrt(128)

    const float* Qg = Qg_ + (((size_t)b * HH  + h  ) * TT + q0) * DD;
    const float* Kg = Kg_ + (((size_t)b * HKV + hkv) * TT     ) * DD;
    const float* Vg = Vg_ + (((size_t)b * HKV + hkv) * TT     ) * DD;

    if (tid < 64) { m_s[tid] = -INFINITY; l_s[tid] = 0.f; }

    // load Q tile
#pragma unroll
    for (int it = 0; it < 8; it++) {
        int idx = tid + it * 256;
        int row = idx >> 5;
        int col = (idx & 31) << 2;
        *(float4*)(Qs + row * 132 + col) = *(const float4*)(Qg + (size_t)idx * 4);
    }

    const int ty = tid >> 4, tx = tid & 15;   // register-tile mapping (S and PV)
    const int r  = tid >> 2, g  = tid & 3;    // softmax mapping (4 threads/row)

    float Oacc[4][8];
#pragma unroll
    for (int i = 0; i < 4; i++)
#pragma unroll
        for (int j = 0; j < 8; j++) Oacc[i][j] = 0.f;

    for (int kt = 0; kt <= qt; kt++) {
        __syncthreads();   // prev PV done with Ss/Vs; Q/m/l init on iter 0

        const float* kg = Kg + (size_t)kt * 64 * DD;
        const float* vg = Vg + (size_t)kt * 64 * DD;
#pragma unroll
        for (int it = 0; it < 8; it++) {
            int idx = tid + it * 256;
            int row = idx >> 5;
            int col = (idx & 31) << 2;
            *(float4*)(Ks + row * 132 + col) = *(const float4*)(kg + (size_t)idx * 4);
            *(float4*)(Vs + row * 132 + col) = *(const float4*)(vg + (size_t)idx * 4);
        }
        __syncthreads();

        // S = Q @ K^T
        float acc[4][4];
#pragma unroll
        for (int i = 0; i < 4; i++)
#pragma unroll
            for (int j = 0; j < 4; j++) acc[i][j] = 0.f;

#pragma unroll 4
        for (int k4 = 0; k4 < 32; k4++) {
            float4 af[4], bf[4];
#pragma unroll
            for (int i = 0; i < 4; i++) af[i] = *(const float4*)(Qs + (ty + 16*i) * 132 + k4 * 4);
#pragma unroll
            for (int j = 0; j < 4; j++) bf[j] = *(const float4*)(Ks + (tx + 16*j) * 132 + k4 * 4);
#pragma unroll
            for (int i = 0; i < 4; i++)
#pragma unroll
                for (int j = 0; j < 4; j++) {
                    acc[i][j] += af[i].x * bf[j].x;
                    acc[i][j] += af[i].y * bf[j].y;
                    acc[i][j] += af[i].z * bf[j].z;
                    acc[i][j] += af[i].w * bf[j].w;
                }
        }

        const bool diag = (kt == qt);
#pragma unroll
        for (int i = 0; i < 4; i++)
#pragma unroll
            for (int j = 0; j < 4; j++) {
                int rr = ty + 16*i, cc = tx + 16*j;
                float v = acc[i][j] * scale;
                if (diag && cc > rr) v = -INFINITY;
                Ss[rr * 65 + cc] = v;
            }
        __syncthreads();

        // online softmax: 4 threads per row
        {
            float mold = m_s[r];
            float mx = mold;
#pragma unroll
            for (int c = 0; c < 16; c++) mx = fmaxf(mx, Ss[r * 65 + g * 16 + c]);
            mx = fmaxf(mx, __shfl_xor_sync(0xffffffffu, mx, 1));
            mx = fmaxf(mx, __shfl_xor_sync(0xffffffffu, mx, 2));

            float corr = expf(mold - mx);
            float psum = 0.f;
#pragma unroll
            for (int c = 0; c < 16; c++) {
                float p = expf(Ss[r * 65 + g * 16 + c] - mx);
                Ss[r * 65 + g * 16 + c] = p;
                psum += p;
            }
            psum += __shfl_xor_sync(0xffffffffu, psum, 1);
            psum += __shfl_xor_sync(0xffffffffu, psum, 2);
            if (g == 0) {
                l_s[r] = l_s[r] * corr + psum;
                m_s[r] = mx;
                corr_s[r] = corr;
            }
        }
        __syncthreads();

        // O = O*corr + P @ V  (register tile: rows ty+16i, cols tx+16j)
#pragma unroll
        for (int i = 0; i < 4; i++) {
            float cf = corr_s[ty + 16*i];
#pragma unroll
            for (int j = 0; j < 8; j++) Oacc[i][j] *= cf;
        }
        for (int s = 0; s < 64; s++) {
            float af[4], bf[8];
#pragma unroll
            for (int i = 0; i < 4; i++) af[i] = Ss[(ty + 16*i) * 65 + s];
#pragma unroll
            for (int j = 0; j < 8; j++) bf[j] = Vs[s * 132 + tx + 16*j];
#pragma unroll
            for (int i = 0; i < 4; i++)
#pragma unroll
                for (int j = 0; j < 8; j++)
                    Oacc[i][j] += af[i] * bf[j];
        }
    }

    // write O (attn layout [B,T,H*D])
#pragma unroll
    for (int i = 0; i < 4; i++) {
        int rr = ty + 16*i;
        float invl = 1.0f / l_s[rr];
        float* outp = Og + (((size_t)b * TT + q0 + rr) * HH + h) * DD;
#pragma unroll
        for (int j = 0; j < 8; j++)
            outp[tx + 16*j] = Oacc[i][j] * invl;
    }
}

// ---------------- launch ----------------
extern "C" void kernel_launch(void* const* d_in, const int* in_sizes, int n_in,
                              void* d_out, int out_size) {
    const float* x  = (const float*)d_in[0];
    // d_in[1] = mask (tril, implicit in flash kernel)
    const float* wq = (const float*)d_in[2];
    const float* wk = (const float*)d_in[3];
    const float* wv = (const float*)d_in[4];
    const float* wo = (const float*)d_in[5];
    float* out = (float*)d_out;

    float *qlin, *klin, *vlin, *q, *k, *v, *attn;
    cudaGetSymbolAddress((void**)&qlin, g_qlin);
    cudaGetSymbolAddress((void**)&klin, g_klin);
    cudaGetSymbolAddress((void**)&vlin, g_vlin);
    cudaGetSymbolAddress((void**)&q,    g_q);
    cudaGetSymbolAddress((void**)&k,    g_k);
    cudaGetSymbolAddress((void**)&v,    g_v);
    cudaGetSymbolAddress((void**)&attn, g_attn);

    const int M = BB * TT;    // 4096

    // QKV projections (tf32 tensor cores)
    tf32gemm_kernel<<<dim3(HH*DD/128,  M/128), 256>>>(x, wq, qlin, M, HH*DD,  EE);
    tf32gemm_kernel<<<dim3(HKV*DD/128, M/128), 256>>>(x, wk, klin, M, HKV*DD, EE);
    tf32gemm_kernel<<<dim3(HKV*DD/128, M/128), 256>>>(x, wv, vlin, M, HKV*DD, EE);

    // RoPE + layout transforms
    {
        int tq = BB * TT * HH  * (DD/2);
        int tk = BB * TT * HKV * (DD/2);
        int tv = BB * TT * HKV * DD;
        rope_kernel<<<(tq + 255)/256, 256>>>(qlin, q, HH);
        rope_kernel<<<(tk + 255)/256, 256>>>(klin, k, HKV);
        vtrans_kernel<<<(tv + 255)/256, 256>>>(vlin, v);
    }

    // Flash attention
    {
        size_t smem = 29696 * sizeof(float);   // 118784 B
        cudaFuncSetAttribute(flash_kernel, cudaFuncAttributeMaxDynamicSharedMemorySize, (int)smem);
        flash_kernel<<<dim3(TT/64, HH, BB), 256, smem>>>(q, k, v, attn);
    }

    // Output projection (tf32 tensor cores)
    tf32gemm_kernel<<<dim3(EE/128, M/128), 256>>>(attn, wo, out, M, EE, EE);
}

// round 5
// speedup vs baseline: 5.0863x; 1.3480x over previous
#include <cuda_runtime.h>
#include <math.h>
#include <stdint.h>

#define BB 2
#define TT 2048
#define EE 2048
#define HH 16
#define HKV 8
#define DD 128
#define QTILE 128
#define KTILE 64

// ---------------- scratch (static device globals; no allocation) ----------------
__device__ float g_qlin[BB*TT*HH*DD];     // [B,T,H*D]   x@wq
__device__ float g_klin[BB*TT*HKV*DD];    // [B,T,HKV*D] x@wk
__device__ float g_vlin[BB*TT*HKV*DD];    // [B,T,HKV*D] x@wv
__device__ float g_q[BB*HH*TT*DD];        // [B,H,T,D]   rope(q)
__device__ float g_k[BB*HKV*TT*DD];       // [B,HKV,T,D] rope(k)
__device__ float g_v[BB*HKV*TT*DD];       // [B,HKV,T,D] v transposed
__device__ float g_attn[BB*TT*HH*DD];     // [B,T,H*D]   attention output

__device__ __forceinline__ uint32_t f2tf(float x) {
    uint32_t u;
    asm("cvt.rna.tf32.f32 %0, %1;" : "=r"(u) : "f"(x));
    return u;
}

__device__ __forceinline__ void mma_tf32(float* d, const uint32_t* a, const uint32_t* b) {
    asm volatile(
        "mma.sync.aligned.m16n8k8.row.col.f32.tf32.tf32.f32 "
        "{%0,%1,%2,%3}, {%4,%5,%6,%7}, {%8,%9}, {%0,%1,%2,%3};"
        : "+f"(d[0]), "+f"(d[1]), "+f"(d[2]), "+f"(d[3])
        : "r"(a[0]), "r"(a[1]), "r"(a[2]), "r"(a[3]), "r"(b[0]), "r"(b[1]));
}

// fast exp on the FMA pipe (no MUFU). Valid for x <= 0 (clamped below -87ish).
__device__ __forceinline__ float fexp(float x) {
    float z = x * 1.4426950408889634f;
    z = fmaxf(z, -126.0f);
    float r = z + 12582912.0f;                       // round-to-nearest via magic
    int   n = __float_as_int(r) - 0x4B400000;        // integer part
    float f = z - (r - 12582912.0f);                 // frac in [-0.5, 0.5]
    float p = 0.0013333558f;
    p = fmaf(p, f, 0.0096181291f);
    p = fmaf(p, f, 0.0555041087f);
    p = fmaf(p, f, 0.2402265069f);
    p = fmaf(p, f, 0.6931471806f);
    p = fmaf(p, f, 1.0f);
    return __int_as_float((n + 127) << 23) * p;
}

// ---------------- tf32 tensor-core GEMM: C[M,N] = A[M,K] @ B[K,N] row-major ----
__global__ void tf32gemm_kernel(const float* __restrict__ A, const float* __restrict__ Bm,
                                float* __restrict__ C, int M, int N, int K) {
    __shared__ uint32_t As[32][136];   // [k][m]
    __shared__ uint32_t Bs[32][136];   // [k][n]

    const int tid  = threadIdx.x;
    const int brow = blockIdx.y * 128;
    const int bcol = blockIdx.x * 128;
    const int lane = tid & 31, warp = tid >> 5;
    const int wr = warp >> 2, wc = warp & 3;
    const int m_base = wr * 64, n_base = wc * 32;
    const int lr = lane >> 2, lc = lane & 3;

    float acc[4][4][4];
#pragma unroll
    for (int mt = 0; mt < 4; mt++)
#pragma unroll
        for (int nt = 0; nt < 4; nt++)
#pragma unroll
            for (int i = 0; i < 4; i++) acc[mt][nt][i] = 0.f;

    const int arow = tid >> 1;
    const int ak0  = (tid & 1) * 16;
    const int bkr  = tid >> 3;
    const int bn0  = (tid & 7) * 4;

    for (int k0 = 0; k0 < K; k0 += 32) {
#pragma unroll
        for (int i = 0; i < 4; i++) {
            float4 a = *(const float4*)(A + (size_t)(brow + arow) * K + k0 + ak0 + i * 4);
            int kk = ak0 + i * 4;
            As[kk + 0][arow] = f2tf(a.x);
            As[kk + 1][arow] = f2tf(a.y);
            As[kk + 2][arow] = f2tf(a.z);
            As[kk + 3][arow] = f2tf(a.w);
        }
#pragma unroll
        for (int i = 0; i < 4; i++) {
            float4 b = *(const float4*)(Bm + (size_t)(k0 + bkr) * N + bcol + bn0 + i * 32);
            uint32_t* p = &Bs[bkr][bn0 + i * 32];
            p[0] = f2tf(b.x); p[1] = f2tf(b.y); p[2] = f2tf(b.z); p[3] = f2tf(b.w);
        }
        __syncthreads();

#pragma unroll
        for (int ks = 0; ks < 4; ks++) {
            const int kk = ks * 8;
            uint32_t afr[4][4], bfr[4][2];
#pragma unroll
            for (int mt = 0; mt < 4; mt++) {
                int m0 = m_base + mt * 16;
                afr[mt][0] = As[kk + lc][m0 + lr];
                afr[mt][1] = As[kk + lc][m0 + lr + 8];
                afr[mt][2] = As[kk + 4 + lc][m0 + lr];
                afr[mt][3] = As[kk + 4 + lc][m0 + lr + 8];
            }
#pragma unroll
            for (int nt = 0; nt < 4; nt++) {
                int n0 = n_base + nt * 8;
                bfr[nt][0] = Bs[kk + lc][n0 + lr];
                bfr[nt][1] = Bs[kk + 4 + lc][n0 + lr];
            }
#pragma unroll
            for (int mt = 0; mt < 4; mt++)
#pragma unroll
                for (int nt = 0; nt < 4; nt++)
                    mma_tf32(acc[mt][nt], afr[mt], bfr[nt]);
        }
        __syncthreads();
    }

#pragma unroll
    for (int mt = 0; mt < 4; mt++)
#pragma unroll
        for (int nt = 0; nt < 4; nt++) {
            int row = brow + m_base + mt * 16 + lr;
            int col = bcol + n_base + nt * 8 + lc * 2;
            *(float2*)(C + (size_t)row * N + col)       = make_float2(acc[mt][nt][0], acc[mt][nt][1]);
            *(float2*)(C + (size_t)(row + 8) * N + col) = make_float2(acc[mt][nt][2], acc[mt][nt][3]);
        }
}

// ---------------- RoPE + [B,T,Hx,D] -> [B,Hx,T,D] ----------------
__global__ void rope_kernel(const float* __restrict__ lin, float* __restrict__ out, int Hx) {
    int idx = blockIdx.x * blockDim.x + threadIdx.x;
    int total = BB * TT * Hx * (DD / 2);
    if (idx >= total) return;
    int j = idx & 63;
    int h = (idx >> 6) % Hx;
    int t = (idx / (64 * Hx)) % TT;
    int b = idx / (64 * Hx * TT);

    float inv = 1.0f / powf(10000.0f, (float)j * (1.0f / 64.0f));
    float ang = (float)t * inv;
    float s, c;
    sincosf(ang, &s, &c);

    const float* p = lin + (((size_t)b * TT + t) * Hx + h) * DD;
    float q1 = p[2*j];
    float q2 = p[2*j + 1];
    float* o = out + (((size_t)b * Hx + h) * TT + t) * DD;
    o[j]      = q1 * c - q2 * s;
    o[j + 64] = q2 * c + q1 * s;
}

// ---------------- V: [B,T,HKV,D] -> [B,HKV,T,D] ----------------
__global__ void vtrans_kernel(const float* __restrict__ lin, float* __restrict__ out) {
    int idx = blockIdx.x * blockDim.x + threadIdx.x;
    int total = BB * TT * HKV * DD;
    if (idx >= total) return;
    int d = idx & 127;
    int h = (idx >> 7) & 7;
    int t = (idx >> 10) % TT;
    int b = idx / (1024 * TT);
    out[(((size_t)b * HKV + h) * TT + t) * DD + d] = lin[idx];
}

// ---------------- Tensor-core flash attention (tf32 mma, causal) ----------------
// grid: (T/128, H, B); 256 threads (8 warps). Warp w owns S rows [16w,16w+16).
// QK^T uses 3-mma residual compensation (near-fp32 logits); PV single tf32.
__global__ __launch_bounds__(256, 1)
void flash_kernel(const float* __restrict__ Qg_, const float* __restrict__ Kg_,
                  const float* __restrict__ Vg_, float* __restrict__ Og) {
    extern __shared__ uint32_t smu[];
    float*    Qs = (float*)smu;          // 128 x 132 (f32, pre-scaled)
    uint32_t* Kh = smu + 16896;          // 64 x 132 (tf32 hi)
    uint32_t* Kl = Kh + 8448;            // 64 x 132 (tf32 lo)
    uint32_t* Vs = Kl + 8448;            // 64 x 136 (tf32)
    uint32_t* Ps = Vs + 8704;            // 128 x 68 (tf32)

    const int tid = threadIdx.x;
    const int qt = blockIdx.x, h = blockIdx.y, b = blockIdx.z;
    const int q0 = qt * QTILE;
    const int hkv = h & (HKV - 1);       // jnp.tile head mapping
    const int warp = tid >> 5, lane = tid & 31;
    const int lr = lane >> 2, lc = lane & 3;
    const int m0 = warp * 16;
    const int ra = m0 + lr, rb = ra + 8;
    const int grow_a = q0 + ra, grow_b = q0 + rb;
    const float scale = 0.08838834764831845f;   // 1/sqrt(128)

    const float* Qg = Qg_ + (((size_t)b * HH  + h  ) * TT + q0) * DD;
    const float* Kg = Kg_ + (((size_t)b * HKV + hkv) * TT) * DD;
    const float* Vg = Vg_ + (((size_t)b * HKV + hkv) * TT) * DD;

    // load Q tile, pre-scaled (128x128 -> 4096 float4)
#pragma unroll
    for (int it = 0; it < 16; it++) {
        int idx = tid + it * 256;
        int row = idx >> 5, c4 = (idx & 31) << 2;
        float4 q = *(const float4*)(Qg + (size_t)idx * 4);
        q.x *= scale; q.y *= scale; q.z *= scale; q.w *= scale;
        *(float4*)(Qs + row * 132 + c4) = q;
    }

    float O[16][4];
#pragma unroll
    for (int nb = 0; nb < 16; nb++)
#pragma unroll
        for (int i = 0; i < 4; i++) O[nb][i] = 0.f;
    float m_a = -1e30f, m_b = -1e30f, l_a = 0.f, l_b = 0.f;

    const int nkt = 2 * qt + 2;
    for (int kt = 0; kt < nkt; kt++) {
        __syncthreads();   // prev-iter consumers done with Kh/Kl/Vs (and Q visible, iter 0)

        const float* kg = Kg + (size_t)kt * KTILE * DD;
        const float* vg = Vg + (size_t)kt * KTILE * DD;
#pragma unroll
        for (int it = 0; it < 8; it++) {         // 2048 float4 (K and V each)
            int idx = tid + it * 256;
            int row = idx >> 5, c4 = (idx & 31) << 2;
            float4 kv = *(const float4*)(kg + (size_t)idx * 4);
            float4 vv = *(const float4*)(vg + (size_t)idx * 4);
            uint32_t h0 = f2tf(kv.x), h1 = f2tf(kv.y), h2 = f2tf(kv.z), h3 = f2tf(kv.w);
            uint4 uh = make_uint4(h0, h1, h2, h3);
            uint4 ul = make_uint4(f2tf(kv.x - __uint_as_float(h0)),
                                  f2tf(kv.y - __uint_as_float(h1)),
                                  f2tf(kv.z - __uint_as_float(h2)),
                                  f2tf(kv.w - __uint_as_float(h3)));
            uint4 uv = make_uint4(f2tf(vv.x), f2tf(vv.y), f2tf(vv.z), f2tf(vv.w));
            *(uint4*)(Kh + row * 132 + c4) = uh;
            *(uint4*)(Kl + row * 132 + c4) = ul;
            *(uint4*)(Vs + row * 136 + c4) = uv;
        }
        __syncthreads();

        // ---- S = Q @ K^T with residual compensation ----
        float S[8][4];
#pragma unroll
        for (int nb = 0; nb < 8; nb++)
#pragma unroll
            for (int i = 0; i < 4; i++) S[nb][i] = 0.f;

#pragma unroll
        for (int ks = 0; ks < 16; ks++) {
            const int k0 = ks * 8;
            float qa0 = Qs[ra * 132 + k0 + lc];
            float qa1 = Qs[rb * 132 + k0 + lc];
            float qa2 = Qs[ra * 132 + k0 + lc + 4];
            float qa3 = Qs[rb * 132 + k0 + lc + 4];
            uint32_t ah[4] = { f2tf(qa0), f2tf(qa1), f2tf(qa2), f2tf(qa3) };
            uint32_t al[4] = { f2tf(qa0 - __uint_as_float(ah[0])),
                               f2tf(qa1 - __uint_as_float(ah[1])),
                               f2tf(qa2 - __uint_as_float(ah[2])),
                               f2tf(qa3 - __uint_as_float(ah[3])) };
#pragma unroll
            for (int nb = 0; nb < 8; nb++) {
                const int n0 = nb * 8;
                uint32_t bh[2] = { Kh[(n0 + lr) * 132 + k0 + lc],
                                   Kh[(n0 + lr) * 132 + k0 + lc + 4] };
                uint32_t bl[2] = { Kl[(n0 + lr) * 132 + k0 + lc],
                                   Kl[(n0 + lr) * 132 + k0 + lc + 4] };
                mma_tf32(S[nb], ah, bh);
                mma_tf32(S[nb], al, bh);
                mma_tf32(S[nb], ah, bl);
            }
        }

        // ---- causal mask (only tiles overlapping the diagonal) ----
        const int s0 = kt * KTILE;
        if (kt >= 2 * qt) {
#pragma unroll
            for (int nb = 0; nb < 8; nb++) {
                int col = s0 + nb * 8 + 2 * lc;
                if (col     > grow_a) S[nb][0] = -1e30f;
                if (col + 1 > grow_a) S[nb][1] = -1e30f;
                if (col     > grow_b) S[nb][2] = -1e30f;
                if (col + 1 > grow_b) S[nb][3] = -1e30f;
            }
        }

        // ---- online softmax (stats in registers; rows ra, rb) ----
        float mxa = m_a, mxb = m_b;
#pragma unroll
        for (int nb = 0; nb < 8; nb++) {
            mxa = fmaxf(mxa, fmaxf(S[nb][0], S[nb][1]));
            mxb = fmaxf(mxb, fmaxf(S[nb][2], S[nb][3]));
        }
        mxa = fmaxf(mxa, __shfl_xor_sync(0xffffffffu, mxa, 1));
        mxa = fmaxf(mxa, __shfl_xor_sync(0xffffffffu, mxa, 2));
        mxb = fmaxf(mxb, __shfl_xor_sync(0xffffffffu, mxb, 1));
        mxb = fmaxf(mxb, __shfl_xor_sync(0xffffffffu, mxb, 2));

        float corr_a = fexp(m_a - mxa);
        float corr_b = fexp(m_b - mxb);
        m_a = mxa; m_b = mxb;

        float suma = 0.f, sumb = 0.f;
#pragma unroll
        for (int nb = 0; nb < 8; nb++) {
            float p0 = fexp(S[nb][0] - mxa);
            float p1 = fexp(S[nb][1] - mxa);
            float p2 = fexp(S[nb][2] - mxb);
            float p3 = fexp(S[nb][3] - mxb);
            suma += p0 + p1;
            sumb += p2 + p3;
            *(uint2*)(Ps + ra * 68 + nb * 8 + 2 * lc) = make_uint2(f2tf(p0), f2tf(p1));
            *(uint2*)(Ps + rb * 68 + nb * 8 + 2 * lc) = make_uint2(f2tf(p2), f2tf(p3));
        }
        suma += __shfl_xor_sync(0xffffffffu, suma, 1);
        suma += __shfl_xor_sync(0xffffffffu, suma, 2);
        sumb += __shfl_xor_sync(0xffffffffu, sumb, 1);
        sumb += __shfl_xor_sync(0xffffffffu, sumb, 2);
        l_a = l_a * corr_a + suma;
        l_b = l_b * corr_b + sumb;

#pragma unroll
        for (int nb = 0; nb < 16; nb++) {
            O[nb][0] *= corr_a; O[nb][1] *= corr_a;
            O[nb][2] *= corr_b; O[nb][3] *= corr_b;
        }
        __syncwarp();   // P stores visible within warp (P is warp-private)

        // ---- O += P @ V ----
#pragma unroll
        for (int ks = 0; ks < 8; ks++) {
            const int k0 = ks * 8;
            uint32_t a[4] = { Ps[ra * 68 + k0 + lc],
                              Ps[rb * 68 + k0 + lc],
                              Ps[ra * 68 + k0 + lc + 4],
                              Ps[rb * 68 + k0 + lc + 4] };
#pragma unroll
            for (int nb = 0; nb < 16; nb++) {
                uint32_t bv[2] = { Vs[(k0 + lc) * 136 + nb * 8 + lr],
                                   Vs[(k0 + lc + 4) * 136 + nb * 8 + lr] };
                mma_tf32(O[nb], a, bv);
            }
        }
    }

    // ---- epilogue: normalize + write [B,T,H*D] ----
    float inva = 1.0f / l_a, invb = 1.0f / l_b;
    float* oa = Og + (((size_t)b * TT + q0 + ra) * HH + h) * DD;
    float* ob = Og + (((size_t)b * TT + q0 + rb) * HH + h) * DD;
#pragma unroll
    for (int nb = 0; nb < 16; nb++) {
        int col = nb * 8 + 2 * lc;
        *(float2*)(oa + col) = make_float2(O[nb][0] * inva, O[nb][1] * inva);
        *(float2*)(ob + col) = make_float2(O[nb][2] * invb, O[nb][3] * invb);
    }
}

// ---------------- launch ----------------
extern "C" void kernel_launch(void* const* d_in, const int* in_sizes, int n_in,
                              void* d_out, int out_size) {
    const float* x  = (const float*)d_in[0];
    // d_in[1] = mask (tril, implicit in flash kernel)
    const float* wq = (const float*)d_in[2];
    const float* wk = (const float*)d_in[3];
    const float* wv = (const float*)d_in[4];
    const float* wo = (const float*)d_in[5];
    float* out = (float*)d_out;

    float *qlin, *klin, *vlin, *q, *k, *v, *attn;
    cudaGetSymbolAddress((void**)&qlin, g_qlin);
    cudaGetSymbolAddress((void**)&klin, g_klin);
    cudaGetSymbolAddress((void**)&vlin, g_vlin);
    cudaGetSymbolAddress((void**)&q,    g_q);
    cudaGetSymbolAddress((void**)&k,    g_k);
    cudaGetSymbolAddress((void**)&v,    g_v);
    cudaGetSymbolAddress((void**)&attn, g_attn);

    const int M = BB * TT;    // 4096

    // QKV projections (tf32 tensor cores)
    tf32gemm_kernel<<<dim3(HH*DD/128,  M/128), 256>>>(x, wq, qlin, M, HH*DD,  EE);
    tf32gemm_kernel<<<dim3(HKV*DD/128, M/128), 256>>>(x, wk, klin, M, HKV*DD, EE);
    tf32gemm_kernel<<<dim3(HKV*DD/128, M/128), 256>>>(x, wv, vlin, M, HKV*DD, EE);

    // RoPE + layout transforms
    {
        int tq = BB * TT * HH  * (DD/2);
        int tk = BB * TT * HKV * (DD/2);
        int tv = BB * TT * HKV * DD;
        rope_kernel<<<(tq + 255)/256, 256>>>(qlin, q, HH);
        rope_kernel<<<(tk + 255)/256, 256>>>(klin, k, HKV);
        vtrans_kernel<<<(tv + 255)/256, 256>>>(vlin, v);
    }

    // Tensor-core flash attention (200 KB dynamic smem, 1 CTA/SM)
    {
        size_t smem = 51200 * sizeof(uint32_t);   // 204800 B
        cudaFuncSetAttribute(flash_kernel, cudaFuncAttributeMaxDynamicSharedMemorySize, (int)smem);
        flash_kernel<<<dim3(TT/QTILE, HH, BB), 256, smem>>>(q, k, v, attn);
    }

    // Output projection (tf32 tensor cores)
    tf32gemm_kernel<<<dim3(EE/128, M/128), 256>>>(attn, wo, out, M, EE, EE);
}

// round 6
// speedup vs baseline: 6.0646x; 1.1924x over previous
#include <cuda_runtime.h>
#include <math.h>
#include <stdint.h>

#define BB 2
#define TT 2048
#define EE 2048
#define HH 16
#define HKV 8
#define DD 128
#define QTILE 128
#define KTILE 64

// ---------------- scratch (static device globals; no allocation) ----------------
__device__ float g_q[BB*HH*TT*DD];        // [B,H,T,D]   rope(x@wq)
__device__ float g_k[BB*HKV*TT*DD];       // [B,HKV,T,D] rope(x@wk)
__device__ float g_v[BB*HKV*TT*DD];       // [B,HKV,T,D] (x@wv) transposed
__device__ float g_attn[BB*TT*HH*DD];     // [B,T,H*D]   attention output

__device__ __forceinline__ uint32_t f2tf(float x) {
    uint32_t u;
    asm("cvt.rna.tf32.f32 %0, %1;" : "=r"(u) : "f"(x));
    return u;
}

__device__ __forceinline__ void mma_tf32(float* d, const uint32_t* a, const uint32_t* b) {
    asm volatile(
        "mma.sync.aligned.m16n8k8.row.col.f32.tf32.tf32.f32 "
        "{%0,%1,%2,%3}, {%4,%5,%6,%7}, {%8,%9}, {%0,%1,%2,%3};"
        : "+f"(d[0]), "+f"(d[1]), "+f"(d[2]), "+f"(d[3])
        : "r"(a[0]), "r"(a[1]), "r"(a[2]), "r"(a[3]), "r"(b[0]), "r"(b[1]));
}

__device__ __forceinline__ void cp16(uint32_t saddr, const void* gptr) {
    asm volatile("cp.async.cg.shared.global [%0], [%1], 16;" :: "r"(saddr), "l"(gptr));
}

// fast exp on the FMA pipe (no MUFU). Valid for x <= 0.
__device__ __forceinline__ float fexp(float x) {
    float z = x * 1.4426950408889634f;
    z = fmaxf(z, -126.0f);
    float r = z + 12582912.0f;
    int   n = __float_as_int(r) - 0x4B400000;
    float f = z - (r - 12582912.0f);
    float p = 0.0013333558f;
    p = fmaf(p, f, 0.0096181291f);
    p = fmaf(p, f, 0.0555041087f);
    p = fmaf(p, f, 0.2402265069f);
    p = fmaf(p, f, 0.6931471806f);
    p = fmaf(p, f, 1.0f);
    return __int_as_float((n + 127) << 23) * p;
}

// ---------------- pipelined tf32 GEMM: C = A[M,K] @ B[K,N], fused epilogues ----
// EPI: 0 = plain row-major store, 1 = RoPE -> [B,Hx,T,D], 2 = transpose -> [B,Hx,T,D]
// 128x128 tile, BK=32, 2-stage cp.async, 256 threads (2 CTAs/SM).
#define A_ST 36
#define B_ST 136

template<int EPI>
__global__ __launch_bounds__(256, 2)
void gemm_kernel(const float* __restrict__ A, const float* __restrict__ Bm,
                 float* __restrict__ C, int M, int N, int K, int Hx) {
    extern __shared__ float smf[];
    float* As = smf;                     // [2][128*36]
    float* Bs = smf + 2 * 128 * A_ST;    // [2][32*136]

    const int tid  = threadIdx.x;
    const int brow = blockIdx.y * 128;
    const int bcol = blockIdx.x * 128;
    const int lane = tid & 31, warp = tid >> 5;
    const int wr = warp >> 2, wc = warp & 3;
    const int m_base = wr * 64, n_base = wc * 32;
    const int lr = lane >> 2, lc = lane & 3;

    float acc[4][4][4];
#pragma unroll
    for (int mt = 0; mt < 4; mt++)
#pragma unroll
        for (int nt = 0; nt < 4; nt++)
#pragma unroll
            for (int i = 0; i < 4; i++) acc[mt][nt][i] = 0.f;

    const uint32_t as_base = (uint32_t)__cvta_generic_to_shared(As);
    const uint32_t bs_base = (uint32_t)__cvta_generic_to_shared(Bs);

    // cp.async tile loader: 1024 16B chunks per tile for A and B each -> 4 per thread
    const int a_row = tid >> 1;                 // with i*... see below
    // A: chunk id = tid + i*256 ; row = id>>3 (0..127), c4 = (id&7)*4
    // B: chunk id = tid + i*256 ; row = id>>5 (0..31),  c4 = (id&31)*4

#define LOAD_TILE(K0, BUF)                                                              \
    {                                                                                   \
        _Pragma("unroll")                                                               \
        for (int i = 0; i < 4; i++) {                                                   \
            int id = tid + i * 256;                                                     \
            int ar = id >> 3, ac = (id & 7) * 4;                                        \
            cp16(as_base + ((BUF) * 128 * A_ST + ar * A_ST + ac) * 4,                   \
                 A + (size_t)(brow + ar) * K + (K0) + ac);                              \
            int br = id >> 5, bc = (id & 31) * 4;                                       \
            cp16(bs_base + ((BUF) * 32 * B_ST + br * B_ST + bc) * 4,                    \
                 Bm + (size_t)((K0) + br) * N + bcol + bc);                             \
        }                                                                               \
        asm volatile("cp.async.commit_group;");                                         \
    }

    const int NIT = K >> 5;
    LOAD_TILE(0, 0);

    for (int it = 0; it < NIT; it++) {
        if (it + 1 < NIT) {
            LOAD_TILE((it + 1) << 5, (it + 1) & 1);
            asm volatile("cp.async.wait_group 1;");
        } else {
            asm volatile("cp.async.wait_group 0;");
        }
        __syncthreads();

        const float* Ab = As + (it & 1) * 128 * A_ST;
        const float* Bb = Bs + (it & 1) * 32 * B_ST;
#pragma unroll
        for (int ks = 0; ks < 4; ks++) {
            const int kk = ks * 8;
            uint32_t afr[4][4], bfr[4][2];
#pragma unroll
            for (int mt = 0; mt < 4; mt++) {
                int m0 = m_base + mt * 16 + lr;
                afr[mt][0] = f2tf(Ab[m0 * A_ST + kk + lc]);
                afr[mt][1] = f2tf(Ab[(m0 + 8) * A_ST + kk + lc]);
                afr[mt][2] = f2tf(Ab[m0 * A_ST + kk + lc + 4]);
                afr[mt][3] = f2tf(Ab[(m0 + 8) * A_ST + kk + lc + 4]);
            }
#pragma unroll
            for (int nt = 0; nt < 4; nt++) {
                int n0 = n_base + nt * 8 + lr;
                bfr[nt][0] = f2tf(Bb[(kk + lc) * B_ST + n0]);
                bfr[nt][1] = f2tf(Bb[(kk + 4 + lc) * B_ST + n0]);
            }
#pragma unroll
            for (int mt = 0; mt < 4; mt++)
#pragma unroll
                for (int nt = 0; nt < 4; nt++)
                    mma_tf32(acc[mt][nt], afr[mt], bfr[nt]);
        }
        __syncthreads();
    }

    // ---------------- epilogue ----------------
#pragma unroll
    for (int mt = 0; mt < 4; mt++)
#pragma unroll
        for (int nt = 0; nt < 4; nt++) {
            int row = brow + m_base + mt * 16 + lr;
            int col = bcol + n_base + nt * 8 + 2 * lc;
            float c0 = acc[mt][nt][0], c1 = acc[mt][nt][1];
            float c2 = acc[mt][nt][2], c3 = acc[mt][nt][3];
            if (EPI == 0) {
                *(float2*)(C + (size_t)row * N + col)       = make_float2(c0, c1);
                *(float2*)(C + (size_t)(row + 8) * N + col) = make_float2(c2, c3);
            } else if (EPI == 1) {
                // RoPE: (c0,c1) are the (2j, 2j+1) pair of row t; (c2,c3) of row t+8
                int b = row >> 11, t = row & (TT - 1);
                int h = col >> 7, j = (col & 127) >> 1;
                float inv = exp2f(-0.20762050593045952f * (float)j);  // 10000^(-j/64)
                float s1, cs1, s2, cs2;
                sincosf((float)t * inv, &s1, &cs1);
                sincosf((float)(t + 8) * inv, &s2, &cs2);
                float* base = C + (((size_t)b * Hx + h) * TT + t) * DD;
                base[j]          = c0 * cs1 - c1 * s1;
                base[j + 64]     = c1 * cs1 + c0 * s1;
                base[8 * DD + j]      = c2 * cs2 - c3 * s2;
                base[8 * DD + j + 64] = c3 * cs2 + c2 * s2;
            } else {
                // transpose: [b,t][h,d] -> [b,h,t,d]
                int b = row >> 11, t = row & (TT - 1);
                int h = col >> 7, d = col & 127;
                float* base = C + (((size_t)b * Hx + h) * TT + t) * DD + d;
                *(float2*)base            = make_float2(c0, c1);
                *(float2*)(base + 8 * DD) = make_float2(c2, c3);
            }
        }
}

// ---------------- Tensor-core flash attention (tf32 mma, causal) ----------------
// grid: (T/128, H, B); 256 threads (8 warps). Warp w owns S rows [16w,16w+16).
// QK^T uses 3-mma residual compensation (near-fp32 logits); PV single tf32.
__global__ __launch_bounds__(256, 1)
void flash_kernel(const float* __restrict__ Qg_, const float* __restrict__ Kg_,
                  const float* __restrict__ Vg_, float* __restrict__ Og) {
    extern __shared__ uint32_t smu[];
    float*    Qs = (float*)smu;          // 128 x 132 (f32, pre-scaled)
    uint32_t* Kh = smu + 16896;          // 64 x 132 (tf32 hi)
    uint32_t* Kl = Kh + 8448;            // 64 x 132 (tf32 lo)
    uint32_t* Vs = Kl + 8448;            // 64 x 136 (tf32)
    uint32_t* Ps = Vs + 8704;            // 128 x 68 (tf32)

    const int tid = threadIdx.x;
    const int qt = blockIdx.x, h = blockIdx.y, b = blockIdx.z;
    const int q0 = qt * QTILE;
    const int hkv = h & (HKV - 1);       // jnp.tile head mapping
    const int warp = tid >> 5, lane = tid & 31;
    const int lr = lane >> 2, lc = lane & 3;
    const int m0 = warp * 16;
    const int ra = m0 + lr, rb = ra + 8;
    const int grow_a = q0 + ra, grow_b = q0 + rb;
    const float scale = 0.08838834764831845f;   // 1/sqrt(128)

    const float* Qg = Qg_ + (((size_t)b * HH  + h  ) * TT + q0) * DD;
    const float* Kg = Kg_ + (((size_t)b * HKV + hkv) * TT) * DD;
    const float* Vg = Vg_ + (((size_t)b * HKV + hkv) * TT) * DD;

    // load Q tile, pre-scaled (128x128 -> 4096 float4)
#pragma unroll
    for (int it = 0; it < 16; it++) {
        int idx = tid + it * 256;
        int row = idx >> 5, c4 = (idx & 31) << 2;
        float4 q = *(const float4*)(Qg + (size_t)idx * 4);
        q.x *= scale; q.y *= scale; q.z *= scale; q.w *= scale;
        *(float4*)(Qs + row * 132 + c4) = q;
    }

    float O[16][4];
#pragma unroll
    for (int nb = 0; nb < 16; nb++)
#pragma unroll
        for (int i = 0; i < 4; i++) O[nb][i] = 0.f;
    float m_a = -1e30f, m_b = -1e30f, l_a = 0.f, l_b = 0.f;

    const int nkt = 2 * qt + 2;
    for (int kt = 0; kt < nkt; kt++) {
        __syncthreads();

        const float* kg = Kg + (size_t)kt * KTILE * DD;
        const float* vg = Vg + (size_t)kt * KTILE * DD;
#pragma unroll
        for (int it = 0; it < 8; it++) {
            int idx = tid + it * 256;
            int row = idx >> 5, c4 = (idx & 31) << 2;
            float4 kv = *(const float4*)(kg + (size_t)idx * 4);
            float4 vv = *(const float4*)(vg + (size_t)idx * 4);
            uint32_t h0 = f2tf(kv.x), h1 = f2tf(kv.y), h2 = f2tf(kv.z), h3 = f2tf(kv.w);
            uint4 uh = make_uint4(h0, h1, h2, h3);
            uint4 ul = make_uint4(f2tf(kv.x - __uint_as_float(h0)),
                                  f2tf(kv.y - __uint_as_float(h1)),
                                  f2tf(kv.z - __uint_as_float(h2)),
                                  f2tf(kv.w - __uint_as_float(h3)));
            uint4 uv = make_uint4(f2tf(vv.x), f2tf(vv.y), f2tf(vv.z), f2tf(vv.w));
            *(uint4*)(Kh + row * 132 + c4) = uh;
            *(uint4*)(Kl + row * 132 + c4) = ul;
            *(uint4*)(Vs + row * 136 + c4) = uv;
        }
        __syncthreads();

        // ---- S = Q @ K^T with residual compensation ----
        float S[8][4];
#pragma unroll
        for (int nb = 0; nb < 8; nb++)
#pragma unroll
            for (int i = 0; i < 4; i++) S[nb][i] = 0.f;

#pragma unroll
        for (int ks = 0; ks < 16; ks++) {
            const int k0 = ks * 8;
            float qa0 = Qs[ra * 132 + k0 + lc];
            float qa1 = Qs[rb * 132 + k0 + lc];
            float qa2 = Qs[ra * 132 + k0 + lc + 4];
            float qa3 = Qs[rb * 132 + k0 + lc + 4];
            uint32_t ah[4] = { f2tf(qa0), f2tf(qa1), f2tf(qa2), f2tf(qa3) };
            uint32_t al[4] = { f2tf(qa0 - __uint_as_float(ah[0])),
                               f2tf(qa1 - __uint_as_float(ah[1])),
                               f2tf(qa2 - __uint_as_float(ah[2])),
                               f2tf(qa3 - __uint_as_float(ah[3])) };
#pragma unroll
            for (int nb = 0; nb < 8; nb++) {
                const int n0 = nb * 8;
                uint32_t bh[2] = { Kh[(n0 + lr) * 132 + k0 + lc],
                                   Kh[(n0 + lr) * 132 + k0 + lc + 4] };
                uint32_t bl[2] = { Kl[(n0 + lr) * 132 + k0 + lc],
                                   Kl[(n0 + lr) * 132 + k0 + lc + 4] };
                mma_tf32(S[nb], ah, bh);
                mma_tf32(S[nb], al, bh);
                mma_tf32(S[nb], ah, bl);
            }
        }

        // ---- causal mask ----
        const int s0 = kt * KTILE;
        if (kt >= 2 * qt) {
#pragma unroll
            for (int nb = 0; nb < 8; nb++) {
                int col = s0 + nb * 8 + 2 * lc;
                if (col     > grow_a) S[nb][0] = -1e30f;
                if (col + 1 > grow_a) S[nb][1] = -1e30f;
                if (col     > grow_b) S[nb][2] = -1e30f;
                if (col + 1 > grow_b) S[nb][3] = -1e30f;
            }
        }

        // ---- online softmax ----
        float mxa = m_a, mxb = m_b;
#pragma unroll
        for (int nb = 0; nb < 8; nb++) {
            mxa = fmaxf(mxa, fmaxf(S[nb][0], S[nb][1]));
            mxb = fmaxf(mxb, fmaxf(S[nb][2], S[nb][3]));
        }
        mxa = fmaxf(mxa, __shfl_xor_sync(0xffffffffu, mxa, 1));
        mxa = fmaxf(mxa, __shfl_xor_sync(0xffffffffu, mxa, 2));
        mxb = fmaxf(mxb, __shfl_xor_sync(0xffffffffu, mxb, 1));
        mxb = fmaxf(mxb, __shfl_xor_sync(0xffffffffu, mxb, 2));

        float corr_a = fexp(m_a - mxa);
        float corr_b = fexp(m_b - mxb);
        m_a = mxa; m_b = mxb;

        float suma = 0.f, sumb = 0.f;
#pragma unroll
        for (int nb = 0; nb < 8; nb++) {
            float p0 = fexp(S[nb][0] - mxa);
            float p1 = fexp(S[nb][1] - mxa);
            float p2 = fexp(S[nb][2] - mxb);
            float p3 = fexp(S[nb][3] - mxb);
            suma += p0 + p1;
            sumb += p2 + p3;
            *(uint2*)(Ps + ra * 68 + nb * 8 + 2 * lc) = make_uint2(f2tf(p0), f2tf(p1));
            *(uint2*)(Ps + rb * 68 + nb * 8 + 2 * lc) = make_uint2(f2tf(p2), f2tf(p3));
        }
        suma += __shfl_xor_sync(0xffffffffu, suma, 1);
        suma += __shfl_xor_sync(0xffffffffu, suma, 2);
        sumb += __shfl_xor_sync(0xffffffffu, sumb, 1);
        sumb += __shfl_xor_sync(0xffffffffu, sumb, 2);
        l_a = l_a * corr_a + suma;
        l_b = l_b * corr_b + sumb;

#pragma unroll
        for (int nb = 0; nb < 16; nb++) {
            O[nb][0] *= corr_a; O[nb][1] *= corr_a;
            O[nb][2] *= corr_b; O[nb][3] *= corr_b;
        }
        __syncwarp();

        // ---- O += P @ V ----
#pragma unroll
        for (int ks = 0; ks < 8; ks++) {
            const int k0 = ks * 8;
            uint32_t a[4] = { Ps[ra * 68 + k0 + lc],
                              Ps[rb * 68 + k0 + lc],
                              Ps[ra * 68 + k0 + lc + 4],
                              Ps[rb * 68 + k0 + lc + 4] };
#pragma unroll
            for (int nb = 0; nb < 16; nb++) {
                uint32_t bv[2] = { Vs[(k0 + lc) * 136 + nb * 8 + lr],
                                   Vs[(k0 + lc + 4) * 136 + nb * 8 + lr] };
                mma_tf32(O[nb], a, bv);
            }
        }
    }

    // ---- epilogue: normalize + write [B,T,H*D] ----
    float inva = 1.0f / l_a, invb = 1.0f / l_b;
    float* oa = Og + (((size_t)b * TT + q0 + ra) * HH + h) * DD;
    float* ob = Og + (((size_t)b * TT + q0 + rb) * HH + h) * DD;
#pragma unroll
    for (int nb = 0; nb < 16; nb++) {
        int col = nb * 8 + 2 * lc;
        *(float2*)(oa + col) = make_float2(O[nb][0] * inva, O[nb][1] * inva);
        *(float2*)(ob + col) = make_float2(O[nb][2] * invb, O[nb][3] * invb);
    }
}

// ---------------- launch ----------------
extern "C" void kernel_launch(void* const* d_in, const int* in_sizes, int n_in,
                              void* d_out, int out_size) {
    const float* x  = (const float*)d_in[0];
    // d_in[1] = mask (tril, implicit in flash kernel)
    const float* wq = (const float*)d_in[2];
    const float* wk = (const float*)d_in[3];
    const float* wv = (const float*)d_in[4];
    const float* wo = (const float*)d_in[5];
    float* out = (float*)d_out;

    float *q, *k, *v, *attn;
    cudaGetSymbolAddress((void**)&q,    g_q);
    cudaGetSymbolAddress((void**)&k,    g_k);
    cudaGetSymbolAddress((void**)&v,    g_v);
    cudaGetSymbolAddress((void**)&attn, g_attn);

    const int M = BB * TT;    // 4096
    const size_t gsmem = (2 * 128 * A_ST + 2 * 32 * B_ST) * sizeof(float);  // 71680

    cudaFuncSetAttribute(gemm_kernel<0>, cudaFuncAttributeMaxDynamicSharedMemorySize, (int)gsmem);
    cudaFuncSetAttribute(gemm_kernel<1>, cudaFuncAttributeMaxDynamicSharedMemorySize, (int)gsmem);
    cudaFuncSetAttribute(gemm_kernel<2>, cudaFuncAttributeMaxDynamicSharedMemorySize, (int)gsmem);

    // QKV projections with fused RoPE / transpose epilogues
    gemm_kernel<1><<<dim3(HH*DD/128,  M/128), 256, gsmem>>>(x, wq, q, M, HH*DD,  EE, HH);
    gemm_kernel<1><<<dim3(HKV*DD/128, M/128), 256, gsmem>>>(x, wk, k, M, HKV*DD, EE, HKV);
    gemm_kernel<2><<<dim3(HKV*DD/128, M/128), 256, gsmem>>>(x, wv, v, M, HKV*DD, EE, HKV);

    // Tensor-core flash attention (200 KB dynamic smem, 1 CTA/SM)
    {
        size_t smem = 51200 * sizeof(uint32_t);   // 204800 B
        cudaFuncSetAttribute(flash_kernel, cudaFuncAttributeMaxDynamicSharedMemorySize, (int)smem);
        flash_kernel<<<dim3(TT/QTILE, HH, BB), 256, smem>>>(q, k, v, attn);
    }

    // Output projection
    gemm_kernel<0><<<dim3(EE/128, M/128), 256, gsmem>>>(attn, wo, out, M, EE, EE, 0);
}

// round 8
// speedup vs baseline: 6.2574x; 1.0318x over previous
#include <cuda_runtime.h>
#include <math.h>
#include <stdint.h>

#define BB 2
#define TT 2048
#define EE 2048
#define HH 16
#define HKV 8
#define DD 128
#define QTILE 128
#define KT32 32
#define NT32 (TT/KT32)      // 64 kv tiles
#define SCALE 0.08838834764831845f

// ---------------- scratch (static device globals; no allocation) ----------------
__device__ float    g_q[BB*HH*TT*DD];                 // [B,H,T,D] rope(x@wq)*scale, fp32
__device__ uint32_t g_kx[BB*HKV*NT32*16*32*4*4];      // packed K: tile/kb/row/lc/{h,h4,l,l4}
__device__ uint32_t g_vf[BB*HKV*NT32*4*128*4*2];      // packed V: tile/kb/d/lc/{v,v4}
__device__ float    g_attn[BB*TT*HH*DD];              // [B,T,H*D]

__device__ __forceinline__ uint32_t f2tf(float x) {
    uint32_t u;
    asm("cvt.rna.tf32.f32 %0, %1;" : "=r"(u) : "f"(x));
    return u;
}

__device__ __forceinline__ void mma_tf32(float* d, const uint32_t* a, const uint32_t* b) {
    asm volatile(
        "mma.sync.aligned.m16n8k8.row.col.f32.tf32.tf32.f32 "
        "{%0,%1,%2,%3}, {%4,%5,%6,%7}, {%8,%9}, {%0,%1,%2,%3};"
        : "+f"(d[0]), "+f"(d[1]), "+f"(d[2]), "+f"(d[3])
        : "r"(a[0]), "r"(a[1]), "r"(a[2]), "r"(a[3]), "r"(b[0]), "r"(b[1]));
}

__device__ __forceinline__ void cp16(uint32_t saddr, const void* gptr) {
    asm volatile("cp.async.cg.shared.global [%0], [%1], 16;" :: "r"(saddr), "l"(gptr));
}

// fast exp on the FMA pipe (no MUFU). Valid for x <= 0.
__device__ __forceinline__ float fexp(float x) {
    float z = x * 1.4426950408889634f;
    z = fmaxf(z, -126.0f);
    float r = z + 12582912.0f;
    int   n = __float_as_int(r) - 0x4B400000;
    float f = z - (r - 12582912.0f);
    float p = 0.0013333558f;
    p = fmaf(p, f, 0.0096181291f);
    p = fmaf(p, f, 0.0555041087f);
    p = fmaf(p, f, 0.2402265069f);
    p = fmaf(p, f, 0.6931471806f);
    p = fmaf(p, f, 1.0f);
    return __int_as_float((n + 127) << 23) * p;
}

// ---------------- pipelined tf32 GEMM: C = A[M,K] @ B[K,N], fused epilogues ----
// EPI: 0 plain store | 1 rope+scale -> g_q fp32 | 3 rope+split+pack -> g_kx | 4 cvt+pack -> g_vf
#define A_ST 36
#define B_ST 136

template<int EPI>
__global__ __launch_bounds__(256, 2)
void gemm_kernel(const float* __restrict__ A, const float* __restrict__ Bm,
                 void* __restrict__ Cout, int M, int N, int K) {
    extern __shared__ float smf[];
    float* As = smf;                     // [2][128*36]
    float* Bs = smf + 2 * 128 * A_ST;    // [2][32*136]

    const int tid  = threadIdx.x;
    const int brow = blockIdx.y * 128;
    const int bcol = blockIdx.x * 128;
    const int lane = tid & 31, warp = tid >> 5;
    const int wr = warp >> 2, wc = warp & 3;
    const int m_base = wr * 64, n_base = wc * 32;
    const int lr = lane >> 2, lc = lane & 3;

    float acc[4][4][4];
#pragma unroll
    for (int mt = 0; mt < 4; mt++)
#pragma unroll
        for (int nt = 0; nt < 4; nt++)
#pragma unroll
            for (int i = 0; i < 4; i++) acc[mt][nt][i] = 0.f;

    const uint32_t as_base = (uint32_t)__cvta_generic_to_shared(As);
    const uint32_t bs_base = (uint32_t)__cvta_generic_to_shared(Bs);

#define LOAD_TILE(K0, BUF)                                                              \
    {                                                                                   \
        _Pragma("unroll")                                                               \
        for (int i = 0; i < 4; i++) {                                                   \
            int id = tid + i * 256;                                                     \
            int ar = id >> 3, ac = (id & 7) * 4;                                        \
            cp16(as_base + ((BUF) * 128 * A_ST + ar * A_ST + ac) * 4,                   \
                 A + (size_t)(brow + ar) * K + (K0) + ac);                              \
            int br = id >> 5, bc = (id & 31) * 4;                                       \
            cp16(bs_base + ((BUF) * 32 * B_ST + br * B_ST + bc) * 4,                    \
                 Bm + (size_t)((K0) + br) * N + bcol + bc);                             \
        }                                                                               \
        asm volatile("cp.async.commit_group;");                                         \
    }

    const int NIT = K >> 5;
    LOAD_TILE(0, 0);

    for (int it = 0; it < NIT; it++) {
        if (it + 1 < NIT) {
            LOAD_TILE((it + 1) << 5, (it + 1) & 1);
            asm volatile("cp.async.wait_group 1;");
        } else {
            asm volatile("cp.async.wait_group 0;");
        }
        __syncthreads();

        const float* Ab = As + (it & 1) * 128 * A_ST;
        const float* Bb = Bs + (it & 1) * 32 * B_ST;
#pragma unroll
        for (int ks = 0; ks < 4; ks++) {
            const int kk = ks * 8;
            uint32_t afr[4][4], bfr[4][2];
#pragma unroll
            for (int mt = 0; mt < 4; mt++) {
                int m0 = m_base + mt * 16 + lr;
                afr[mt][0] = f2tf(Ab[m0 * A_ST + kk + lc]);
                afr[mt][1] = f2tf(Ab[(m0 + 8) * A_ST + kk + lc]);
                afr[mt][2] = f2tf(Ab[m0 * A_ST + kk + lc + 4]);
                afr[mt][3] = f2tf(Ab[(m0 + 8) * A_ST + kk + lc + 4]);
            }
#pragma unroll
            for (int nt = 0; nt < 4; nt++) {
                int n0 = n_base + nt * 8 + lr;
                bfr[nt][0] = f2tf(Bb[(kk + lc) * B_ST + n0]);
                bfr[nt][1] = f2tf(Bb[(kk + 4 + lc) * B_ST + n0]);
            }
#pragma unroll
            for (int mt = 0; mt < 4; mt++)
#pragma unroll
                for (int nt = 0; nt < 4; nt++)
                    mma_tf32(acc[mt][nt], afr[mt], bfr[nt]);
        }
        __syncthreads();
    }

    // ---------------- epilogue ----------------
#pragma unroll
    for (int mt = 0; mt < 4; mt++)
#pragma unroll
        for (int nt = 0; nt < 4; nt++) {
            int row = brow + m_base + mt * 16 + lr;
            int col = bcol + n_base + nt * 8 + 2 * lc;
            float c0 = acc[mt][nt][0], c1 = acc[mt][nt][1];
            float c2 = acc[mt][nt][2], c3 = acc[mt][nt][3];
            if (EPI == 0) {
                float* C = (float*)Cout;
                *(float2*)(C + (size_t)row * N + col)       = make_float2(c0, c1);
                *(float2*)(C + (size_t)(row + 8) * N + col) = make_float2(c2, c3);
            } else if (EPI == 1) {
                // Q: rope + scale -> [B,H,T,D] fp32
                float* C = (float*)Cout;
                int b = row >> 11, t = row & (TT - 1);
                int h = col >> 7, j = (col & 127) >> 1;
                float inv = exp2f(-0.20762050593045952f * (float)j);
                float s1, cs1, s2, cs2;
                sincosf((float)t * inv, &s1, &cs1);
                sincosf((float)(t + 8) * inv, &s2, &cs2);
                float* base = C + (((size_t)b * HH + h) * TT + t) * DD;
                base[j]               = (c0 * cs1 - c1 * s1) * SCALE;
                base[j + 64]          = (c1 * cs1 + c0 * s1) * SCALE;
                base[8 * DD + j]      = (c2 * cs2 - c3 * s2) * SCALE;
                base[8 * DD + j + 64] = (c3 * cs2 + c2 * s2) * SCALE;
            } else if (EPI == 3) {
                // K: rope + tf32 hi/lo split + fragment-packed layout
                uint32_t* C = (uint32_t*)Cout;
                int b = row >> 11, t = row & (TT - 1);
                int h = col >> 7, j = (col & 127) >> 1;
                float inv = exp2f(-0.20762050593045952f * (float)j);
                float s1, cs1, s2, cs2;
                sincosf((float)t * inv, &s1, &cs1);
                sincosf((float)(t + 8) * inv, &s2, &cs2);
                float va = c0 * cs1 - c1 * s1;        // (t,   j)
                float vb = c1 * cs1 + c0 * s1;        // (t,   j+64)
                float vc = c2 * cs2 - c3 * s2;        // (t+8, j)
                float vd = c3 * cs2 + c2 * s2;        // (t+8, j+64)
                size_t bh = (size_t)(b * HKV + h) * NT32;
#pragma unroll
                for (int e = 0; e < 4; e++) {
                    int tt = (e < 2) ? t : t + 8;
                    int d  = (e & 1) ? j + 64 : j;
                    float val = (e == 0) ? va : (e == 1) ? vb : (e == 2) ? vc : vd;
                    int tile = tt >> 5, r = tt & 31, kb = d >> 3, c = d & 7;
                    int lcx = c & 3, hi = c >> 2;
                    uint32_t* p = C + (((bh + tile) * 16 + kb) * 32 + r) * 16 + lcx * 4;
                    uint32_t hv = f2tf(val);
                    p[hi]     = hv;
                    p[2 + hi] = f2tf(val - __uint_as_float(hv));
                }
            } else {
                // V: tf32 cvt + fragment-packed layout
                uint32_t* C = (uint32_t*)Cout;
                int b = row >> 11, t = row & (TT - 1);
                int h = col >> 7, d = col & 127;
                size_t bh = (size_t)(b * HKV + h) * NT32;
#pragma unroll
                for (int e = 0; e < 4; e++) {
                    int tt = (e < 2) ? t : t + 8;
                    int dd = d + (e & 1);
                    float val = (e == 0) ? c0 : (e == 1) ? c1 : (e == 2) ? c2 : c3;
                    int tile = tt >> 5, kb = (tt & 31) >> 3, lct = tt & 3, pi = (tt & 7) >> 2;
                    C[(((bh + tile) * 4 + kb) * 128 + dd) * 8 + lct * 2 + pi] = f2tf(val);
                }
            }
        }
}

// ---------------- Tensor-core flash attention (tf32 mma, causal) ----------------
// grid: (T/128, H, B); 256 threads (8 warps). cp.async double-buffered KV tiles
// of 32 rows, pre-split/pre-packed in global. 3-mma compensated QK^T, tf32 PV.
__global__ __launch_bounds__(256, 1)
void flash_kernel(const float* __restrict__ Qg_, const uint32_t* __restrict__ KXg,
                  const uint32_t* __restrict__ VFg, float* __restrict__ Og) {
    extern __shared__ uint32_t smu[];
    float*    Qs = (float*)smu;            // 128 x 132 fp32 (pre-scaled)
    uint32_t* KX = smu + 16896;            // 2 x 8192  (packed K tile: 32KB each)
    uint32_t* VF = smu + 16896 + 16384;    // 2 x 4096  (packed V tile: 16KB each)
    uint32_t* Ps = smu + 16896 + 16384 + 8192;   // 128 x 36 (tf32 P)

    const int tid = threadIdx.x;
    const int qt = blockIdx.x, h = blockIdx.y, b = blockIdx.z;
    const int q0 = qt * QTILE;
    const int hkv = h & (HKV - 1);
    const int warp = tid >> 5, lane = tid & 31;
    const int lr = lane >> 2, lc = lane & 3;
    const int m0 = warp * 16;
    const int ra = m0 + lr, rb = ra + 8;
    const int grow_a = q0 + ra, grow_b = q0 + rb;

    const float*    Qg = Qg_ + (((size_t)b * HH  + h  ) * TT + q0) * DD;
    const uint32_t* Kt = KXg + (size_t)(b * HKV + hkv) * NT32 * 8192;
    const uint32_t* Vt = VFg + (size_t)(b * HKV + hkv) * NT32 * 4096;

    const uint32_t kx_base = (uint32_t)__cvta_generic_to_shared(KX);
    const uint32_t vf_base = (uint32_t)__cvta_generic_to_shared(VF);

#define KV_ISSUE(KTT, BUF)                                                      \
    {                                                                           \
        _Pragma("unroll")                                                       \
        for (int i = 0; i < 8; i++) {                                           \
            int id = tid + i * 256;                                             \
            cp16(kx_base + ((BUF) * 8192 + id * 4) * 4,                         \
                 Kt + (size_t)(KTT) * 8192 + id * 4);                           \
        }                                                                       \
        _Pragma("unroll")                                                       \
        for (int i = 0; i < 4; i++) {                                           \
            int id = tid + i * 256;                                             \
            cp16(vf_base + ((BUF) * 4096 + id * 4) * 4,                         \
                 Vt + (size_t)(KTT) * 4096 + id * 4);                           \
        }                                                                       \
        asm volatile("cp.async.commit_group;");                                 \
    }

    const int nkt = 4 * (qt + 1);
    KV_ISSUE(0, 0);

    // load Q tile (overlaps tile-0 cp.async)
#pragma unroll
    for (int it = 0; it < 16; it++) {
        int idx = tid + it * 256;
        int row = idx >> 5, c4 = (idx & 31) << 2;
        *(float4*)(Qs + row * 132 + c4) = *(const float4*)(Qg + (size_t)idx * 4);
    }

    float O[16][4];
#pragma unroll
    for (int nb = 0; nb < 16; nb++)
#pragma unroll
        for (int i = 0; i < 4; i++) O[nb][i] = 0.f;
    float m_a = -1e30f, m_b = -1e30f, l_a = 0.f, l_b = 0.f;

    for (int kt = 0; kt < nkt; kt++) {
        asm volatile("cp.async.wait_group 0;");
        __syncthreads();                 // tile kt ready; all warps done with prev buffers
        if (kt + 1 < nkt) KV_ISSUE(kt + 1, (kt + 1) & 1);

        const uint32_t* Kb = KX + (kt & 1) * 8192;
        const uint32_t* Vb = VF + (kt & 1) * 4096;

        // ---- S = Q @ K^T (compensated) ----
        float S[4][4];
#pragma unroll
        for (int nb = 0; nb < 4; nb++)
#pragma unroll
            for (int i = 0; i < 4; i++) S[nb][i] = 0.f;

#pragma unroll
        for (int ks = 0; ks < 16; ks++) {
            const int k0 = ks * 8;
            float qa0 = Qs[ra * 132 + k0 + lc];
            float qa1 = Qs[rb * 132 + k0 + lc];
            float qa2 = Qs[ra * 132 + k0 + lc + 4];
            float qa3 = Qs[rb * 132 + k0 + lc + 4];
            uint32_t ah[4] = { f2tf(qa0), f2tf(qa1), f2tf(qa2), f2tf(qa3) };
            uint32_t al[4] = { f2tf(qa0 - __uint_as_float(ah[0])),
                               f2tf(qa1 - __uint_as_float(ah[1])),
                               f2tf(qa2 - __uint_as_float(ah[2])),
                               f2tf(qa3 - __uint_as_float(ah[3])) };
#pragma unroll
            for (int nb = 0; nb < 4; nb++) {
                uint4 kf = *(const uint4*)(Kb + ((ks * 32 + nb * 8 + lr) * 4 + lc) * 4);
                uint32_t bh[2] = { kf.x, kf.y };
                uint32_t bl[2] = { kf.z, kf.w };
                mma_tf32(S[nb], ah, bh);
                mma_tf32(S[nb], al, bh);
                mma_tf32(S[nb], ah, bl);
            }
        }

        // ---- causal mask (only diagonal-overlapping tiles) ----
        const int s0 = kt * KT32;
        if (kt >= 4 * qt) {
#pragma unroll
            for (int nb = 0; nb < 4; nb++) {
                int col = s0 + nb * 8 + 2 * lc;
                if (col     > grow_a) S[nb][0] = -1e30f;
                if (col + 1 > grow_a) S[nb][1] = -1e30f;
                if (col     > grow_b) S[nb][2] = -1e30f;
                if (col + 1 > grow_b) S[nb][3] = -1e30f;
            }
        }

        // ---- online softmax ----
        float mxa = m_a, mxb = m_b;
#pragma unroll
        for (int nb = 0; nb < 4; nb++) {
            mxa = fmaxf(mxa, fmaxf(S[nb][0], S[nb][1]));
            mxb = fmaxf(mxb, fmaxf(S[nb][2], S[nb][3]));
        }
        mxa = fmaxf(mxa, __shfl_xor_sync(0xffffffffu, mxa, 1));
        mxa = fmaxf(mxa, __shfl_xor_sync(0xffffffffu, mxa, 2));
        mxb = fmaxf(mxb, __shfl_xor_sync(0xffffffffu, mxb, 1));
        mxb = fmaxf(mxb, __shfl_xor_sync(0xffffffffu, mxb, 2));

        float corr_a = fexp(m_a - mxa);
        float corr_b = fexp(m_b - mxb);
        m_a = mxa; m_b = mxb;

        float suma = 0.f, sumb = 0.f;
#pragma unroll
        for (int nb = 0; nb < 4; nb++) {
            float p0 = fexp(S[nb][0] - mxa);
            float p1 = fexp(S[nb][1] - mxa);
            float p2 = fexp(S[nb][2] - mxb);
            float p3 = fexp(S[nb][3] - mxb);
            suma += p0 + p1;
            sumb += p2 + p3;
            *(uint2*)(Ps + ra * 36 + nb * 8 + 2 * lc) = make_uint2(f2tf(p0), f2tf(p1));
            *(uint2*)(Ps + rb * 36 + nb * 8 + 2 * lc) = make_uint2(f2tf(p2), f2tf(p3));
        }
        suma += __shfl_xor_sync(0xffffffffu, suma, 1);
        suma += __shfl_xor_sync(0xffffffffu, suma, 2);
        sumb += __shfl_xor_sync(0xffffffffu, sumb, 1);
        sumb += __shfl_xor_sync(0xffffffffu, sumb, 2);
        l_a = l_a * corr_a + suma;
        l_b = l_b * corr_b + sumb;

#pragma unroll
        for (int nb = 0; nb < 16; nb++) {
            O[nb][0] *= corr_a; O[nb][1] *= corr_a;
            O[nb][2] *= corr_b; O[nb][3] *= corr_b;
        }
        __syncwarp();    // P is warp-private (rows of this warp only)

        // ---- O += P @ V ----
#pragma unroll
        for (int ks = 0; ks < 4; ks++) {
            const int k0 = ks * 8;
            uint32_t a[4] = { Ps[ra * 36 + k0 + lc],
                              Ps[rb * 36 + k0 + lc],
                              Ps[ra * 36 + k0 + lc + 4],
                              Ps[rb * 36 + k0 + lc + 4] };
#pragma unroll
            for (int nb = 0; nb < 16; nb++) {
                uint2 vv = *(const uint2*)(Vb + ((ks * 128 + nb * 8 + lr) * 4 + lc) * 2);
                mma_tf32(O[nb], a, (const uint32_t*)&vv);
            }
        }
    }

    // ---- epilogue: normalize + write [B,T,H*D] ----
    float inva = 1.0f / l_a, invb = 1.0f / l_b;
    float* oa = Og + (((size_t)b * TT + q0 + ra) * HH + h) * DD;
    float* ob = Og + (((size_t)b * TT + q0 + rb) * HH + h) * DD;
#pragma unroll
    for (int nb = 0; nb < 16; nb++) {
        int col = nb * 8 + 2 * lc;
        *(float2*)(oa + col) = make_float2(O[nb][0] * inva, O[nb][1] * inva);
        *(float2*)(ob + col) = make_float2(O[nb][2] * invb, O[nb][3] * invb);
    }
}

// ---------------- launch ----------------
extern "C" void kernel_launch(void* const* d_in, const int* in_sizes, int n_in,
                              void* d_out, int out_size) {
    const float* x  = (const float*)d_in[0];
    const float* wq = (const float*)d_in[2];
    const float* wk = (const float*)d_in[3];
    const float* wv = (const float*)d_in[4];
    const float* wo = (const float*)d_in[5];
    float* out = (float*)d_out;

    float *q, *attn;
    uint32_t *kx, *vf;
    cudaGetSymbolAddress((void**)&q,    g_q);
    cudaGetSymbolAddress((void**)&kx,   g_kx);
    cudaGetSymbolAddress((void**)&vf,   g_vf);
    cudaGetSymbolAddress((void**)&attn, g_attn);

    const int M = BB * TT;    // 4096
    const size_t gsmem = (2 * 128 * A_ST + 2 * 32 * B_ST) * sizeof(float);  // 71680

    cudaFuncSetAttribute(gemm_kernel<0>, cudaFuncAttributeMaxDynamicSharedMemorySize, (int)gsmem);
    cudaFuncSetAttribute(gemm_kernel<1>, cudaFuncAttributeMaxDynamicSharedMemorySize, (int)gsmem);
    cudaFuncSetAttribute(gemm_kernel<3>, cudaFuncAttributeMaxDynamicSharedMemorySize, (int)gsmem);
    cudaFuncSetAttribute(gemm_kernel<4>, cudaFuncAttributeMaxDynamicSharedMemorySize, (int)gsmem);

    // QKV projections with fused rope/split/pack epilogues
    gemm_kernel<1><<<dim3(HH*DD/128,  M/128), 256, gsmem>>>(x, wq, q,  M, HH*DD,  EE);
    gemm_kernel<3><<<dim3(HKV*DD/128, M/128), 256, gsmem>>>(x, wk, kx, M, HKV*DD, EE);
    gemm_kernel<4><<<dim3(HKV*DD/128, M/128), 256, gsmem>>>(x, wv, vf, M, HKV*DD, EE);

    // Flash attention (184 KB dynamic smem)
    {
        size_t smem = (16896 + 16384 + 8192 + 4608) * sizeof(uint32_t);  // 184320 B
        cudaFuncSetAttribute(flash_kernel, cudaFuncAttributeMaxDynamicSharedMemorySize, (int)smem);
        flash_kernel<<<dim3(TT/QTILE, HH, BB), 256, smem>>>(q, kx, vf, attn);
    }

    // Output projection
    gemm_kernel<0><<<dim3(EE/128, M/128), 256, gsmem>>>(attn, wo, out, M, EE, EE);
}

// round 9
// speedup vs baseline: 6.8737x; 1.0985x over previous
#include <cuda_runtime.h>
#include <math.h>
#include <stdint.h>

#define BB 2
#define TT 2048
#define EE 2048
#define HH 16
#define HKV 8
#define DD 128
#define QTILE 128
#define KT32 32
#define NT32 (TT/KT32)      // 64 kv tiles
#define SCALE 0.08838834764831845f

// ---------------- scratch (static device globals; no allocation) ----------------
__device__ float    g_q[BB*HH*TT*DD];                 // [B,H,T,D] rope(x@wq)*scale, fp32
__device__ uint32_t g_kx[BB*HKV*NT32*16*32*4*4];      // packed K: tile/kb/row/lc/{h,h4,l,l4}
__device__ uint32_t g_vf[BB*HKV*NT32*4*128*4*2];      // packed V: tile/kb/d/lc/{v,v4}
__device__ float    g_attn[BB*TT*HH*DD];              // [B,T,H*D]
__device__ float2   g_rope[TT*64];                    // per (t,j) {cos,sin}

__device__ __forceinline__ uint32_t f2tf(float x) {
    uint32_t u;
    asm("cvt.rna.tf32.f32 %0, %1;" : "=r"(u) : "f"(x));
    return u;
}

__device__ __forceinline__ void mma_tf32(float* d, const uint32_t* a, const uint32_t* b) {
    asm volatile(
        "mma.sync.aligned.m16n8k8.row.col.f32.tf32.tf32.f32 "
        "{%0,%1,%2,%3}, {%4,%5,%6,%7}, {%8,%9}, {%0,%1,%2,%3};"
        : "+f"(d[0]), "+f"(d[1]), "+f"(d[2]), "+f"(d[3])
        : "r"(a[0]), "r"(a[1]), "r"(a[2]), "r"(a[3]), "r"(b[0]), "r"(b[1]));
}

__device__ __forceinline__ void cp16(uint32_t saddr, const void* gptr) {
    asm volatile("cp.async.cg.shared.global [%0], [%1], 16;" :: "r"(saddr), "l"(gptr));
}

// ---------------- rope table init ----------------
__global__ void rope_init_kernel() {
    int i = blockIdx.x * 256 + threadIdx.x;     // < TT*64
    int j = i & 63, t = i >> 6;
    float inv = exp2f(-0.20762050593045952f * (float)j);  // 10000^(-j/64)
    float s, c;
    sincosf((float)t * inv, &s, &c);
    g_rope[i] = make_float2(c, s);
}

// ---------------- pipelined tf32 GEMM: C = A[M,K] @ B[K,N], fused epilogues ----
// EPI: 0 plain store | 1 rope+scale -> g_q fp32 | 3 rope+split+pack -> g_kx | 4 cvt+pack -> g_vf
#define A_ST 36
#define B_ST 136

template<int EPI>
__global__ __launch_bounds__(256, 2)
void gemm_kernel(const float* __restrict__ A, const float* __restrict__ Bm,
                 void* __restrict__ Cout, int M, int N, int K) {
    extern __shared__ float smf[];
    float* As = smf;                     // [2][128*36]
    float* Bs = smf + 2 * 128 * A_ST;    // [2][32*136]

    const int tid  = threadIdx.x;
    const int brow = blockIdx.y * 128;
    const int bcol = blockIdx.x * 128;
    const int lane = tid & 31, warp = tid >> 5;
    const int wr = warp >> 2, wc = warp & 3;
    const int m_base = wr * 64, n_base = wc * 32;
    const int lr = lane >> 2, lc = lane & 3;

    float acc[4][4][4];
#pragma unroll
    for (int mt = 0; mt < 4; mt++)
#pragma unroll
        for (int nt = 0; nt < 4; nt++)
#pragma unroll
            for (int i = 0; i < 4; i++) acc[mt][nt][i] = 0.f;

    const uint32_t as_base = (uint32_t)__cvta_generic_to_shared(As);
    const uint32_t bs_base = (uint32_t)__cvta_generic_to_shared(Bs);

#define LOAD_TILE(K0, BUF)                                                              \
    {                                                                                   \
        _Pragma("unroll")                                                               \
        for (int i = 0; i < 4; i++) {                                                   \
            int id = tid + i * 256;                                                     \
            int ar = id >> 3, ac = (id & 7) * 4;                                        \
            cp16(as_base + ((BUF) * 128 * A_ST + ar * A_ST + ac) * 4,                   \
                 A + (size_t)(brow + ar) * K + (K0) + ac);                              \
            int br = id >> 5, bc = (id & 31) * 4;                                       \
            cp16(bs_base + ((BUF) * 32 * B_ST + br * B_ST + bc) * 4,                    \
                 Bm + (size_t)((K0) + br) * N + bcol + bc);                             \
        }                                                                               \
        asm volatile("cp.async.commit_group;");                                         \
    }

    const int NIT = K >> 5;
    LOAD_TILE(0, 0);

    for (int it = 0; it < NIT; it++) {
        if (it + 1 < NIT) {
            LOAD_TILE((it + 1) << 5, (it + 1) & 1);
            asm volatile("cp.async.wait_group 1;");
        } else {
            asm volatile("cp.async.wait_group 0;");
        }
        __syncthreads();

        const float* Ab = As + (it & 1) * 128 * A_ST;
        const float* Bb = Bs + (it & 1) * 32 * B_ST;
#pragma unroll
        for (int ks = 0; ks < 4; ks++) {
            const int kk = ks * 8;
            uint32_t afr[4][4], bfr[4][2];
#pragma unroll
            for (int mt = 0; mt < 4; mt++) {
                int m0 = m_base + mt * 16 + lr;
                afr[mt][0] = f2tf(Ab[m0 * A_ST + kk + lc]);
                afr[mt][1] = f2tf(Ab[(m0 + 8) * A_ST + kk + lc]);
                afr[mt][2] = f2tf(Ab[m0 * A_ST + kk + lc + 4]);
                afr[mt][3] = f2tf(Ab[(m0 + 8) * A_ST + kk + lc + 4]);
            }
#pragma unroll
            for (int nt = 0; nt < 4; nt++) {
                int n0 = n_base + nt * 8 + lr;
                bfr[nt][0] = f2tf(Bb[(kk + lc) * B_ST + n0]);
                bfr[nt][1] = f2tf(Bb[(kk + 4 + lc) * B_ST + n0]);
            }
#pragma unroll
            for (int mt = 0; mt < 4; mt++)
#pragma unroll
                for (int nt = 0; nt < 4; nt++)
                    mma_tf32(acc[mt][nt], afr[mt], bfr[nt]);
        }
        __syncthreads();
    }

    // ---------------- epilogue ----------------
#pragma unroll
    for (int mt = 0; mt < 4; mt++)
#pragma unroll
        for (int nt = 0; nt < 4; nt++) {
            int row = brow + m_base + mt * 16 + lr;
            int col = bcol + n_base + nt * 8 + 2 * lc;
            float c0 = acc[mt][nt][0], c1 = acc[mt][nt][1];
            float c2 = acc[mt][nt][2], c3 = acc[mt][nt][3];
            if (EPI == 0) {
                float* C = (float*)Cout;
                *(float2*)(C + (size_t)row * N + col)       = make_float2(c0, c1);
                *(float2*)(C + (size_t)(row + 8) * N + col) = make_float2(c2, c3);
            } else if (EPI == 1) {
                // Q: rope (table) + scale -> [B,H,T,D] fp32
                float* C = (float*)Cout;
                int b = row >> 11, t = row & (TT - 1);
                int h = col >> 7, j = (col & 127) >> 1;
                float2 r1 = g_rope[t * 64 + j];
                float2 r2 = g_rope[(t + 8) * 64 + j];
                float* base = C + (((size_t)b * HH + h) * TT + t) * DD;
                base[j]               = (c0 * r1.x - c1 * r1.y) * SCALE;
                base[j + 64]          = (c1 * r1.x + c0 * r1.y) * SCALE;
                base[8 * DD + j]      = (c2 * r2.x - c3 * r2.y) * SCALE;
                base[8 * DD + j + 64] = (c3 * r2.x + c2 * r2.y) * SCALE;
            } else if (EPI == 3) {
                // K: rope (table) + tf32 hi/lo split + fragment-packed layout
                uint32_t* C = (uint32_t*)Cout;
                int b = row >> 11, t = row & (TT - 1);
                int h = col >> 7, j = (col & 127) >> 1;
                float2 r1 = g_rope[t * 64 + j];
                float2 r2 = g_rope[(t + 8) * 64 + j];
                float va = c0 * r1.x - c1 * r1.y;     // (t,   j)
                float vb = c1 * r1.x + c0 * r1.y;     // (t,   j+64)
                float vc = c2 * r2.x - c3 * r2.y;     // (t+8, j)
                float vd = c3 * r2.x + c2 * r2.y;     // (t+8, j+64)
                size_t bh = (size_t)(b * HKV + h) * NT32;
#pragma unroll
                for (int e = 0; e < 4; e++) {
                    int tt = (e < 2) ? t : t + 8;
                    int d  = (e & 1) ? j + 64 : j;
                    float val = (e == 0) ? va : (e == 1) ? vb : (e == 2) ? vc : vd;
                    int tile = tt >> 5, r = tt & 31, kb = d >> 3, c = d & 7;
                    int lcx = c & 3, hi = c >> 2;
                    uint32_t* p = C + (((bh + tile) * 16 + kb) * 32 + r) * 16 + lcx * 4;
                    uint32_t hv = f2tf(val);
                    p[hi]     = hv;
                    p[2 + hi] = f2tf(val - __uint_as_float(hv));
                }
            } else {
                // V: tf32 cvt + fragment-packed layout
                uint32_t* C = (uint32_t*)Cout;
                int b = row >> 11, t = row & (TT - 1);
                int h = col >> 7, d = col & 127;
                size_t bh = (size_t)(b * HKV + h) * NT32;
#pragma unroll
                for (int e = 0; e < 4; e++) {
                    int tt = (e < 2) ? t : t + 8;
                    int dd = d + (e & 1);
                    float val = (e == 0) ? c0 : (e == 1) ? c1 : (e == 2) ? c2 : c3;
                    int tile = tt >> 5, kb = (tt & 31) >> 3, lct = tt & 3, pi = (tt & 7) >> 2;
                    C[(((bh + tile) * 4 + kb) * 128 + dd) * 8 + lct * 2 + pi] = f2tf(val);
                }
            }
        }
}

// ---------------- Tensor-core flash attention (tf32 mma, causal) ----------------
// grid: (T/128, H, B); 256 threads (8 warps), heavy tiles first.
// S = ah*(Kh + Kl) (K compensated, Q plain tf32); PV single tf32. MUFU exp.
__global__ __launch_bounds__(256, 1)
void flash_kernel(const float* __restrict__ Qg_, const uint32_t* __restrict__ KXg,
                  const uint32_t* __restrict__ VFg, float* __restrict__ Og) {
    extern __shared__ uint32_t smu[];
    float*    Qs = (float*)smu;            // 128 x 132 fp32 (pre-scaled)
    uint32_t* KX = smu + 16896;            // 2 x 8192  (packed K tile)
    uint32_t* VF = smu + 16896 + 16384;    // 2 x 4096  (packed V tile)
    uint32_t* Ps = smu + 16896 + 16384 + 8192;   // 128 x 36 (tf32 P)

    const int tid = threadIdx.x;
    const int qt = gridDim.x - 1 - blockIdx.x;   // heavy (large-qt) blocks first
    const int h = blockIdx.y, b = blockIdx.z;
    const int q0 = qt * QTILE;
    const int hkv = h & (HKV - 1);
    const int warp = tid >> 5, lane = tid & 31;
    const int lr = lane >> 2, lc = lane & 3;
    const int m0 = warp * 16;
    const int ra = m0 + lr, rb = ra + 8;
    const int grow_a = q0 + ra, grow_b = q0 + rb;

    const float*    Qg = Qg_ + (((size_t)b * HH  + h  ) * TT + q0) * DD;
    const uint32_t* Kt = KXg + (size_t)(b * HKV + hkv) * NT32 * 8192;
    const uint32_t* Vt = VFg + (size_t)(b * HKV + hkv) * NT32 * 4096;

    const uint32_t kx_base = (uint32_t)__cvta_generic_to_shared(KX);
    const uint32_t vf_base = (uint32_t)__cvta_generic_to_shared(VF);

#define KV_ISSUE(KTT, BUF)                                                      \
    {                                                                           \
        _Pragma("unroll")                                                       \
        for (int i = 0; i < 8; i++) {                                           \
            int id = tid + i * 256;                                             \
            cp16(kx_base + ((BUF) * 8192 + id * 4) * 4,                         \
                 Kt + (size_t)(KTT) * 8192 + id * 4);                           \
        }                                                                       \
        _Pragma("unroll")                                                       \
        for (int i = 0; i < 4; i++) {                                           \
            int id = tid + i * 256;                                             \
            cp16(vf_base + ((BUF) * 4096 + id * 4) * 4,                         \
                 Vt + (size_t)(KTT) * 4096 + id * 4);                           \
        }                                                                       \
        asm volatile("cp.async.commit_group;");                                 \
    }

    const int nkt = 4 * (qt + 1);
    KV_ISSUE(0, 0);

    // load Q tile (overlaps tile-0 cp.async)
#pragma unroll
    for (int it = 0; it < 16; it++) {
        int idx = tid + it * 256;
        int row = idx >> 5, c4 = (idx & 31) << 2;
        *(float4*)(Qs + row * 132 + c4) = *(const float4*)(Qg + (size_t)idx * 4);
    }

    float O[16][4];
#pragma unroll
    for (int nb = 0; nb < 16; nb++)
#pragma unroll
        for (int i = 0; i < 4; i++) O[nb][i] = 0.f;
    float m_a = -1e30f, m_b = -1e30f, l_a = 0.f, l_b = 0.f;

    for (int kt = 0; kt < nkt; kt++) {
        asm volatile("cp.async.wait_group 0;");
        __syncthreads();
        if (kt + 1 < nkt) KV_ISSUE(kt + 1, (kt + 1) & 1);

        const uint32_t* Kb = KX + (kt & 1) * 8192;
        const uint32_t* Vb = VF + (kt & 1) * 4096;

        // ---- S = Q(tf32) @ (Kh + Kl)^T ----
        float S[4][4];
#pragma unroll
        for (int nb = 0; nb < 4; nb++)
#pragma unroll
            for (int i = 0; i < 4; i++) S[nb][i] = 0.f;

#pragma unroll
        for (int ks = 0; ks < 16; ks++) {
            const int k0 = ks * 8;
            uint32_t ah[4] = { f2tf(Qs[ra * 132 + k0 + lc]),
                               f2tf(Qs[rb * 132 + k0 + lc]),
                               f2tf(Qs[ra * 132 + k0 + lc + 4]),
                               f2tf(Qs[rb * 132 + k0 + lc + 4]) };
            uint4 kf[4];
#pragma unroll
            for (int nb = 0; nb < 4; nb++)
                kf[nb] = *(const uint4*)(Kb + ((ks * 32 + nb * 8 + lr) * 4 + lc) * 4);
#pragma unroll
            for (int nb = 0; nb < 4; nb++)
                mma_tf32(S[nb], ah, (const uint32_t*)&kf[nb].x);   // hi
#pragma unroll
            for (int nb = 0; nb < 4; nb++)
                mma_tf32(S[nb], ah, (const uint32_t*)&kf[nb].z);   // lo
        }

        // ---- causal mask (only diagonal-overlapping tiles) ----
        const int s0 = kt * KT32;
        if (kt >= 4 * qt) {
#pragma unroll
            for (int nb = 0; nb < 4; nb++) {
                int col = s0 + nb * 8 + 2 * lc;
                if (col     > grow_a) S[nb][0] = -1e30f;
                if (col + 1 > grow_a) S[nb][1] = -1e30f;
                if (col     > grow_b) S[nb][2] = -1e30f;
                if (col + 1 > grow_b) S[nb][3] = -1e30f;
            }
        }

        // ---- online softmax (MUFU exp) ----
        float mxa = m_a, mxb = m_b;
#pragma unroll
        for (int nb = 0; nb < 4; nb++) {
            mxa = fmaxf(mxa, fmaxf(S[nb][0], S[nb][1]));
            mxb = fmaxf(mxb, fmaxf(S[nb][2], S[nb][3]));
        }
        mxa = fmaxf(mxa, __shfl_xor_sync(0xffffffffu, mxa, 1));
        mxa = fmaxf(mxa, __shfl_xor_sync(0xffffffffu, mxa, 2));
        mxb = fmaxf(mxb, __shfl_xor_sync(0xffffffffu, mxb, 1));
        mxb = fmaxf(mxb, __shfl_xor_sync(0xffffffffu, mxb, 2));

        float corr_a = __expf(m_a - mxa);
        float corr_b = __expf(m_b - mxb);
        m_a = mxa; m_b = mxb;

        float suma = 0.f, sumb = 0.f;
#pragma unroll
        for (int nb = 0; nb < 4; nb++) {
            float p0 = __expf(S[nb][0] - mxa);
            float p1 = __expf(S[nb][1] - mxa);
            float p2 = __expf(S[nb][2] - mxb);
            float p3 = __expf(S[nb][3] - mxb);
            suma += p0 + p1;
            sumb += p2 + p3;
            *(uint2*)(Ps + ra * 36 + nb * 8 + 2 * lc) = make_uint2(f2tf(p0), f2tf(p1));
            *(uint2*)(Ps + rb * 36 + nb * 8 + 2 * lc) = make_uint2(f2tf(p2), f2tf(p3));
        }
        suma += __shfl_xor_sync(0xffffffffu, suma, 1);
        suma += __shfl_xor_sync(0xffffffffu, suma, 2);
        sumb += __shfl_xor_sync(0xffffffffu, sumb, 1);
        sumb += __shfl_xor_sync(0xffffffffu, sumb, 2);
        l_a = l_a * corr_a + suma;
        l_b = l_b * corr_b + sumb;

#pragma unroll
        for (int nb = 0; nb < 16; nb++) {
            O[nb][0] *= corr_a; O[nb][1] *= corr_a;
            O[nb][2] *= corr_b; O[nb][3] *= corr_b;
        }
        __syncwarp();    // P is warp-private (rows of this warp only)

        // ---- O += P @ V ----
#pragma unroll
        for (int ks = 0; ks < 4; ks++) {
            const int k0 = ks * 8;
            uint32_t a[4] = { Ps[ra * 36 + k0 + lc],
                              Ps[rb * 36 + k0 + lc],
                              Ps[ra * 36 + k0 + lc + 4],
                              Ps[rb * 36 + k0 + lc + 4] };
#pragma unroll
            for (int nb = 0; nb < 16; nb++) {
                uint2 vv = *(const uint2*)(Vb + ((ks * 128 + nb * 8 + lr) * 4 + lc) * 2);
                mma_tf32(O[nb], a, (const uint32_t*)&vv);
            }
        }
    }

    // ---- epilogue: normalize + write [B,T,H*D] ----
    float inva = 1.0f / l_a, invb = 1.0f / l_b;
    float* oa = Og + (((size_t)b * TT + q0 + ra) * HH + h) * DD;
    float* ob = Og + (((size_t)b * TT + q0 + rb) * HH + h) * DD;
#pragma unroll
    for (int nb = 0; nb < 16; nb++) {
        int col = nb * 8 + 2 * lc;
        *(float2*)(oa + col) = make_float2(O[nb][0] * inva, O[nb][1] * inva);
        *(float2*)(ob + col) = make_float2(O[nb][2] * invb, O[nb][3] * invb);
    }
}

// ---------------- launch ----------------
extern "C" void kernel_launch(void* const* d_in, const int* in_sizes, int n_in,
                              void* d_out, int out_size) {
    const float* x  = (const float*)d_in[0];
    const float* wq = (const float*)d_in[2];
    const float* wk = (const float*)d_in[3];
    const float* wv = (const float*)d_in[4];
    const float* wo = (const float*)d_in[5];
    float* out = (float*)d_out;

    float *q, *attn;
    uint32_t *kx, *vf;
    cudaGetSymbolAddress((void**)&q,    g_q);
    cudaGetSymbolAddress((void**)&kx,   g_kx);
    cudaGetSymbolAddress((void**)&vf,   g_vf);
    cudaGetSymbolAddress((void**)&attn, g_attn);

    const int M = BB * TT;    // 4096
    const size_t gsmem = (2 * 128 * A_ST + 2 * 32 * B_ST) * sizeof(float);  // 71680

    cudaFuncSetAttribute(gemm_kernel<0>, cudaFuncAttributeMaxDynamicSharedMemorySize, (int)gsmem);
    cudaFuncSetAttribute(gemm_kernel<1>, cudaFuncAttributeMaxDynamicSharedMemorySize, (int)gsmem);
    cudaFuncSetAttribute(gemm_kernel<3>, cudaFuncAttributeMaxDynamicSharedMemorySize, (int)gsmem);
    cudaFuncSetAttribute(gemm_kernel<4>, cudaFuncAttributeMaxDynamicSharedMemorySize, (int)gsmem);

    // rope table (deterministic; rebuilt every call)
    rope_init_kernel<<<TT * 64 / 256, 256>>>();

    // QKV projections with fused rope/split/pack epilogues
    gemm_kernel<1><<<dim3(HH*DD/128,  M/128), 256, gsmem>>>(x, wq, q,  M, HH*DD,  EE);
    gemm_kernel<3><<<dim3(HKV*DD/128, M/128), 256, gsmem>>>(x, wk, kx, M, HKV*DD, EE);
    gemm_kernel<4><<<dim3(HKV*DD/128, M/128), 256, gsmem>>>(x, wv, vf, M, HKV*DD, EE);

    // Flash attention (184 KB dynamic smem)
    {
        size_t smem = (16896 + 16384 + 8192 + 4608) * sizeof(uint32_t);  // 184320 B
        cudaFuncSetAttribute(flash_kernel, cudaFuncAttributeMaxDynamicSharedMemorySize, (int)smem);
        flash_kernel<<<dim3(TT/QTILE, HH, BB), 256, smem>>>(q, kx, vf, attn);
    }

    // Output projection
    gemm_kernel<0><<<dim3(EE/128, M/128), 256, gsmem>>>(attn, wo, out, M, EE, EE);
}

// round 10
// speedup vs baseline: 8.3328x; 1.2123x over previous
#include <cuda_runtime.h>
#include <math.h>
#include <stdint.h>

#define BB 2
#define TT 2048
#define EE 2048
#define HH 16
#define HKV 8
#define DD 128
#define QTILE 128
#define KT32 32
#define NT32 (TT/KT32)      // 64 kv tiles
#define SCALE 0.08838834764831845f

// ---------------- scratch (static device globals; no allocation) ----------------
__device__ uint4    g_x4[BB*TT*EE/4];                 // packed-A x (tf32 bits)
__device__ uint2    g_wq2[EE*HH*DD/2];                // packed-B weights (tf32 bits)
__device__ uint2    g_wk2[EE*HKV*DD/2];
__device__ uint2    g_wv2[EE*HKV*DD/2];
__device__ uint2    g_wo2[HH*DD*EE/2];
__device__ uint4    g_q4[BB*HH*TT*DD/4];              // packed-A Q (rope+scale, tf32)
__device__ uint32_t g_kx[BB*HKV*NT32*16*32*4*4];      // packed K: {h,h4,l,l4}
__device__ uint32_t g_vf[BB*HKV*NT32*4*128*4*2];      // packed V: {v,v4}
__device__ uint4    g_attn4[BB*TT*HH*DD/4];           // packed-A attn (tf32)
__device__ float2   g_rope[TT*64];                    // per (t,j) {cos,sin}

__device__ __forceinline__ uint32_t f2tf(float x) {
    uint32_t u;
    asm("cvt.rna.tf32.f32 %0, %1;" : "=r"(u) : "f"(x));
    return u;
}

__device__ __forceinline__ void mma_tf32(float* d, const uint32_t* a, const uint32_t* b) {
    asm volatile(
        "mma.sync.aligned.m16n8k8.row.col.f32.tf32.tf32.f32 "
        "{%0,%1,%2,%3}, {%4,%5,%6,%7}, {%8,%9}, {%0,%1,%2,%3};"
        : "+f"(d[0]), "+f"(d[1]), "+f"(d[2]), "+f"(d[3])
        : "r"(a[0]), "r"(a[1]), "r"(a[2]), "r"(a[3]), "r"(b[0]), "r"(b[1]));
}

__device__ __forceinline__ void cp16(uint32_t saddr, const void* gptr) {
    asm volatile("cp.async.cg.shared.global [%0], [%1], 16;" :: "r"(saddr), "l"(gptr));
}

// ---------------- prepasses ----------------
__global__ void rope_init_kernel() {
    int i = blockIdx.x * 256 + threadIdx.x;     // < TT*64
    int j = i & 63, t = i >> 6;
    float inv = exp2f(-0.20762050593045952f * (float)j);  // 10000^(-j/64)
    float s, c;
    sincosf((float)t * inv, &s, &c);
    g_rope[i] = make_float2(c, s);
}

// x[4096][2048] -> packed-A uint4 fragments {(m,k),(m+8,k),(m,k+4),(m+8,k+4)}
__global__ void pack_x_kernel(const float* __restrict__ x) {
    int id = blockIdx.x * 256 + threadIdx.x;    // < 2097152
    int lc = id & 3, lr = (id >> 2) & 7, kg = (id >> 5) & 255, mb = id >> 13;
    const float* p = x + (size_t)(mb * 16 + lr) * 2048 + kg * 8 + lc;
    g_x4[id] = make_uint4(f2tf(p[0]), f2tf(p[8 * 2048]), f2tf(p[4]), f2tf(p[8 * 2048 + 4]));
}

// w[K=2048][N] -> packed-B uint2 fragments {(k,n),(k+4,n)}; layout [(kg*N+n)*4+lc]
__global__ void pack_w_kernel(const float* __restrict__ w, uint2* __restrict__ out,
                              int N, int nsh) {
    int id = blockIdx.x * 256 + threadIdx.x;    // < 256*N*4
    int lc = id & 3, n = (id >> 2) & (N - 1), kg = id >> (2 + nsh);
    const float* p = w + (size_t)(kg * 8 + lc) * N + n;
    out[id] = make_uint2(f2tf(p[0]), f2tf(p[4 * N]));
}

// ---------------- pipelined tf32 GEMM on pre-packed operands ----------------
// EPI: 0 plain fp32 store | 1 rope+scale -> g_q4 packed | 3 rope+split -> g_kx | 4 -> g_vf
template<int EPI>
__global__ __launch_bounds__(256, 2)
void gemm_kernel(const uint4* __restrict__ A4, const uint2* __restrict__ B2,
                 void* __restrict__ Cout, int M, int N, int K) {
    extern __shared__ uint32_t smu[];
    uint4* As4 = (uint4*)smu;                  // [2][1024] uint4 (16KB/stage)
    uint2* Bs2 = (uint2*)(smu + 2 * 1024 * 4); // [2][2048] uint2 (16KB/stage)

    const int tid  = threadIdx.x;
    const int brow = blockIdx.y * 128;
    const int bcol = blockIdx.x * 128;
    const int lane = tid & 31, warp = tid >> 5;
    const int wr = warp >> 2, wc = warp & 3;
    const int n_base = wc * 32;
    const int lr = lane >> 2, lc = lane & 3;
    const int KG = K >> 3;

    float acc[4][4][4];
#pragma unroll
    for (int mt = 0; mt < 4; mt++)
#pragma unroll
        for (int nt = 0; nt < 4; nt++)
#pragma unroll
            for (int i = 0; i < 4; i++) acc[mt][nt][i] = 0.f;

    const uint32_t as_base = (uint32_t)__cvta_generic_to_shared(As4);
    const uint32_t bs_base = (uint32_t)__cvta_generic_to_shared(Bs2);

#define LOAD_TILE(K0, BUF)                                                              \
    {                                                                                   \
        const int kg0 = (K0) >> 3;                                                      \
        _Pragma("unroll")                                                               \
        for (int i = 0; i < 4; i++) {                                                   \
            int id = tid + i * 256;                                                     \
            int mb = id >> 7, sub = id & 127;                                           \
            cp16(as_base + ((BUF) * 1024 + mb * 128 + sub) * 16,                        \
                 A4 + ((size_t)((brow >> 4) + mb) * KG + kg0 + (sub >> 5)) * 32         \
                    + (sub & 31));                                                      \
            int kgl = id >> 8, s2 = id & 255;                                           \
            int n = s2 >> 1, h2 = (id & 1) * 2;                                         \
            cp16(bs_base + ((BUF) * 2048 + (kgl * 128 + n) * 4 + h2) * 8,               \
                 B2 + ((size_t)(kg0 + kgl) * N + bcol + n) * 4 + h2);                   \
        }                                                                               \
        asm volatile("cp.async.commit_group;");                                         \
    }

    const int NIT = K >> 5;
    LOAD_TILE(0, 0);

    for (int it = 0; it < NIT; it++) {
        if (it + 1 < NIT) {
            LOAD_TILE((it + 1) << 5, (it + 1) & 1);
            asm volatile("cp.async.wait_group 1;");
        } else {
            asm volatile("cp.async.wait_group 0;");
        }
        __syncthreads();

        const uint4* Ab = As4 + (it & 1) * 1024;
        const uint2* Bb = Bs2 + (it & 1) * 2048;
#pragma unroll
        for (int ks = 0; ks < 4; ks++) {
            uint4 afr[4];
            uint2 bfr[4];
#pragma unroll
            for (int mt = 0; mt < 4; mt++)
                afr[mt] = Ab[(wr * 4 + mt) * 128 + ks * 32 + lane];
#pragma unroll
            for (int nt = 0; nt < 4; nt++)
                bfr[nt] = Bb[(ks * 128 + n_base + nt * 8 + lr) * 4 + lc];
#pragma unroll
            for (int mt = 0; mt < 4; mt++)
#pragma unroll
                for (int nt = 0; nt < 4; nt++)
                    mma_tf32(acc[mt][nt], (const uint32_t*)&afr[mt], (const uint32_t*)&bfr[nt]);
        }
        __syncthreads();
    }

    // ---------------- epilogue ----------------
#pragma unroll
    for (int mt = 0; mt < 4; mt++)
#pragma unroll
        for (int nt = 0; nt < 4; nt++) {
            int row = brow + wr * 64 + mt * 16 + lr;
            int col = bcol + n_base + nt * 8 + 2 * lc;
            float c0 = acc[mt][nt][0], c1 = acc[mt][nt][1];
            float c2 = acc[mt][nt][2], c3 = acc[mt][nt][3];
            if (EPI == 0) {
                float* C = (float*)Cout;
                *(float2*)(C + (size_t)row * N + col)       = make_float2(c0, c1);
                *(float2*)(C + (size_t)(row + 8) * N + col) = make_float2(c2, c3);
            } else if (EPI == 1) {
                // Q: rope + scale -> packed-A fragment layout (g_q4)
                int b = row >> 11, t = row & (TT - 1);
                int h = col >> 7, j = (col & 127) >> 1;
                float2 r1 = g_rope[t * 64 + j];
                float2 r2 = g_rope[(t + 8) * 64 + j];
                float va = (c0 * r1.x - c1 * r1.y) * SCALE;   // (t,   j)
                float vb = (c1 * r1.x + c0 * r1.y) * SCALE;   // (t,   j+64)
                float vc = (c2 * r2.x - c3 * r2.y) * SCALE;   // (t+8, j)
                float vd = (c3 * r2.x + c2 * r2.y) * SCALE;   // (t+8, j+64)
                uint32_t* W = (uint32_t*)Cout;
                size_t bh = (size_t)(b * HH + h) * 65536;     // 128*16*32 uint4 per (b,h)
                int mblk = t >> 4, lrq = t & 7;
#pragma unroll
                for (int e = 0; e < 2; e++) {
                    int d = (e == 0) ? j : j + 64;
                    float vh0 = (e == 0) ? va : vb;           // half 0 (row t)
                    float vh1 = (e == 0) ? vc : vd;           // half 1 (row t+8)
                    size_t u4 = bh + (size_t)(mblk * 16 + (d >> 3)) * 32 + lrq * 4 + ((d & 7) & 3);
                    uint32_t* p = W + u4 * 4 + (((d & 7) >> 2) << 1);
                    *(uint2*)p = make_uint2(f2tf(vh0), f2tf(vh1));
                }
            } else if (EPI == 3) {
                // K: rope + tf32 hi/lo split + fragment-packed layout
                uint32_t* C = (uint32_t*)Cout;
                int b = row >> 11, t = row & (TT - 1);
                int h = col >> 7, j = (col & 127) >> 1;
                float2 r1 = g_rope[t * 64 + j];
                float2 r2 = g_rope[(t + 8) * 64 + j];
                float va = c0 * r1.x - c1 * r1.y;
                float vb = c1 * r1.x + c0 * r1.y;
                float vc = c2 * r2.x - c3 * r2.y;
                float vd = c3 * r2.x + c2 * r2.y;
                size_t bh = (size_t)(b * HKV + h) * NT32;
#pragma unroll
                for (int e = 0; e < 4; e++) {
                    int tt = (e < 2) ? t : t + 8;
                    int d  = (e & 1) ? j + 64 : j;
                    float val = (e == 0) ? va : (e == 1) ? vb : (e == 2) ? vc : vd;
                    int tile = tt >> 5, r = tt & 31, kb = d >> 3, c = d & 7;
                    int lcx = c & 3, hi = c >> 2;
                    uint32_t* p = C + (((bh + tile) * 16 + kb) * 32 + r) * 16 + lcx * 4;
                    uint32_t hv = f2tf(val);
                    p[hi]     = hv;
                    p[2 + hi] = f2tf(val - __uint_as_float(hv));
                }
            } else {
                // V: tf32 cvt + fragment-packed layout
                uint32_t* C = (uint32_t*)Cout;
                int b = row >> 11, t = row & (TT - 1);
                int h = col >> 7, d = col & 127;
                size_t bh = (size_t)(b * HKV + h) * NT32;
#pragma unroll
                for (int e = 0; e < 4; e++) {
                    int tt = (e < 2) ? t : t + 8;
                    int dd = d + (e & 1);
                    float val = (e == 0) ? c0 : (e == 1) ? c1 : (e == 2) ? c2 : c3;
                    int tile = tt >> 5, kb = (tt & 31) >> 3, lct = tt & 3, pi = (tt & 7) >> 2;
                    C[(((bh + tile) * 4 + kb) * 128 + dd) * 8 + lct * 2 + pi] = f2tf(val);
                }
            }
        }
}

// ---------------- Tensor-core flash attention (tf32 mma, causal) ----------------
// grid: (T/128, H, B); 256 threads (8 warps), heavy tiles first. Q in registers
// (packed fragments from g_q4); K hi/lo compensated; PV single tf32; MUFU exp.
__global__ __launch_bounds__(256, 1)
void flash_kernel(const uint4* __restrict__ Q4, const uint32_t* __restrict__ KXg,
                  const uint32_t* __restrict__ VFg, uint4* __restrict__ Attn4) {
    extern __shared__ uint32_t smu[];
    uint32_t* KX = smu;                    // 2 x 8192  (packed K tile)
    uint32_t* VF = smu + 16384;            // 2 x 4096  (packed V tile)
    uint32_t* Ps = smu + 16384 + 8192;     // 128 x 36  (tf32 P)

    const int tid = threadIdx.x;
    const int qt = gridDim.x - 1 - blockIdx.x;   // heavy (large-qt) blocks first
    const int h = blockIdx.y, b = blockIdx.z;
    const int q0 = qt * QTILE;
    const int hkv = h & (HKV - 1);
    const int warp = tid >> 5, lane = tid & 31;
    const int lr = lane >> 2, lc = lane & 3;
    const int m0 = warp * 16;
    const int ra = m0 + lr, rb = ra + 8;
    const int grow_a = q0 + ra, grow_b = q0 + rb;

    const uint4*    Qb = Q4 + (size_t)(b * HH + h) * 65536 + (size_t)(qt * 8 + warp) * 512;
    const uint32_t* Kt = KXg + (size_t)(b * HKV + hkv) * NT32 * 8192;
    const uint32_t* Vt = VFg + (size_t)(b * HKV + hkv) * NT32 * 4096;

    const uint32_t kx_base = (uint32_t)__cvta_generic_to_shared(KX);
    const uint32_t vf_base = (uint32_t)__cvta_generic_to_shared(VF);

#define KV_ISSUE(KTT, BUF)                                                      \
    {                                                                           \
        _Pragma("unroll")                                                       \
        for (int i = 0; i < 8; i++) {                                           \
            int id = tid + i * 256;                                             \
            cp16(kx_base + ((BUF) * 8192 + id * 4) * 4,                         \
                 Kt + (size_t)(KTT) * 8192 + id * 4);                           \
        }                                                                       \
        _Pragma("unroll")                                                       \
        for (int i = 0; i < 4; i++) {                                           \
            int id = tid + i * 256;                                             \
            cp16(vf_base + ((BUF) * 4096 + id * 4) * 4,                         \
                 Vt + (size_t)(KTT) * 4096 + id * 4);                           \
        }                                                                       \
        asm volatile("cp.async.commit_group;");                                 \
    }

    const int nkt = 4 * (qt + 1);
    KV_ISSUE(0, 0);

    // Q fragments into registers (coalesced; overlaps tile-0 cp.async)
    uint4 qreg[16];
#pragma unroll
    for (int ks = 0; ks < 16; ks++) qreg[ks] = Qb[ks * 32 + lane];

    float O[16][4];
#pragma unroll
    for (int nb = 0; nb < 16; nb++)
#pragma unroll
        for (int i = 0; i < 4; i++) O[nb][i] = 0.f;
    float m_a = -1e30f, m_b = -1e30f, l_a = 0.f, l_b = 0.f;

    for (int kt = 0; kt < nkt; kt++) {
        asm volatile("cp.async.wait_group 0;");
        __syncthreads();
        if (kt + 1 < nkt) KV_ISSUE(kt + 1, (kt + 1) & 1);

        const uint32_t* Kb = KX + (kt & 1) * 8192;
        const uint32_t* Vb = VF + (kt & 1) * 4096;

        // ---- S = Q @ (Kh + Kl)^T ----
        float S[4][4];
#pragma unroll
        for (int nb = 0; nb < 4; nb++)
#pragma unroll
            for (int i = 0; i < 4; i++) S[nb][i] = 0.f;

#pragma unroll
        for (int ks = 0; ks < 16; ks++) {
            uint4 kf[4];
#pragma unroll
            for (int nb = 0; nb < 4; nb++)
                kf[nb] = *(const uint4*)(Kb + ((ks * 32 + nb * 8 + lr) * 4 + lc) * 4);
#pragma unroll
            for (int nb = 0; nb < 4; nb++)
                mma_tf32(S[nb], (const uint32_t*)&qreg[ks], (const uint32_t*)&kf[nb].x);
#pragma unroll
            for (int nb = 0; nb < 4; nb++)
                mma_tf32(S[nb], (const uint32_t*)&qreg[ks], (const uint32_t*)&kf[nb].z);
        }

        // ---- causal mask (only diagonal-overlapping tiles) ----
        const int s0 = kt * KT32;
        if (kt >= 4 * qt) {
#pragma unroll
            for (int nb = 0; nb < 4; nb++) {
                int col = s0 + nb * 8 + 2 * lc;
                if (col     > grow_a) S[nb][0] = -1e30f;
                if (col + 1 > grow_a) S[nb][1] = -1e30f;
                if (col     > grow_b) S[nb][2] = -1e30f;
                if (col + 1 > grow_b) S[nb][3] = -1e30f;
            }
        }

        // ---- online softmax (MUFU exp) ----
        float mxa = m_a, mxb = m_b;
#pragma unroll
        for (int nb = 0; nb < 4; nb++) {
            mxa = fmaxf(mxa, fmaxf(S[nb][0], S[nb][1]));
            mxb = fmaxf(mxb, fmaxf(S[nb][2], S[nb][3]));
        }
        mxa = fmaxf(mxa, __shfl_xor_sync(0xffffffffu, mxa, 1));
        mxa = fmaxf(mxa, __shfl_xor_sync(0xffffffffu, mxa, 2));
        mxb = fmaxf(mxb, __shfl_xor_sync(0xffffffffu, mxb, 1));
        mxb = fmaxf(mxb, __shfl_xor_sync(0xffffffffu, mxb, 2));

        float corr_a = __expf(m_a - mxa);
        float corr_b = __expf(m_b - mxb);
        m_a = mxa; m_b = mxb;

        float suma = 0.f, sumb = 0.f;
#pragma unroll
        for (int nb = 0; nb < 4; nb++) {
            float p0 = __expf(S[nb][0] - mxa);
            float p1 = __expf(S[nb][1] - mxa);
            float p2 = __expf(S[nb][2] - mxb);
            float p3 = __expf(S[nb][3] - mxb);
            suma += p0 + p1;
            sumb += p2 + p3;
            *(uint2*)(Ps + ra * 36 + nb * 8 + 2 * lc) = make_uint2(f2tf(p0), f2tf(p1));
            *(uint2*)(Ps + rb * 36 + nb * 8 + 2 * lc) = make_uint2(f2tf(p2), f2tf(p3));
        }
        suma += __shfl_xor_sync(0xffffffffu, suma, 1);
        suma += __shfl_xor_sync(0xffffffffu, suma, 2);
        sumb += __shfl_xor_sync(0xffffffffu, sumb, 1);
        sumb += __shfl_xor_sync(0xffffffffu, sumb, 2);
        l_a = l_a * corr_a + suma;
        l_b = l_b * corr_b + sumb;

#pragma unroll
        for (int nb = 0; nb < 16; nb++) {
            O[nb][0] *= corr_a; O[nb][1] *= corr_a;
            O[nb][2] *= corr_b; O[nb][3] *= corr_b;
        }
        __syncwarp();    // P is warp-private (rows of this warp only)

        // ---- O += P @ V ----
#pragma unroll
        for (int ks = 0; ks < 4; ks++) {
            const int k0 = ks * 8;
            uint32_t a[4] = { Ps[ra * 36 + k0 + lc],
                              Ps[rb * 36 + k0 + lc],
                              Ps[ra * 36 + k0 + lc + 4],
                              Ps[rb * 36 + k0 + lc + 4] };
#pragma unroll
            for (int nb = 0; nb < 16; nb++) {
                uint2 vv = *(const uint2*)(Vb + ((ks * 128 + nb * 8 + lr) * 4 + lc) * 2);
                mma_tf32(O[nb], a, (const uint32_t*)&vv);
            }
        }
    }

    // ---- epilogue: normalize + write packed-A attn (tf32 bits) ----
    float inva = 1.0f / l_a, invb = 1.0f / l_b;
    uint32_t* attnW = (uint32_t*)Attn4;
    const int mblk = b * 128 + qt * 8 + warp;
    const int lcp0 = (2 * lc) & 3, lcp1 = (2 * lc + 1) & 3;
    const int hi2  = ((2 * lc) >> 2) << 1;
#pragma unroll
    for (int nb = 0; nb < 16; nb++) {
        size_t sb = ((size_t)(mblk * 256 + h * 16 + nb) * 8 + lr) * 16;
        *(uint2*)(attnW + sb + lcp0 * 4 + hi2) =
            make_uint2(f2tf(O[nb][0] * inva), f2tf(O[nb][2] * invb));
        *(uint2*)(attnW + sb + lcp1 * 4 + hi2) =
            make_uint2(f2tf(O[nb][1] * inva), f2tf(O[nb][3] * invb));
    }
}

// ---------------- launch ----------------
extern "C" void kernel_launch(void* const* d_in, const int* in_sizes, int n_in,
                              void* d_out, int out_size) {
    const float* x  = (const float*)d_in[0];
    const float* wq = (const float*)d_in[2];
    const float* wk = (const float*)d_in[3];
    const float* wv = (const float*)d_in[4];
    const float* wo = (const float*)d_in[5];
    float* out = (float*)d_out;

    uint4 *x4, *q4, *attn4;
    uint2 *wq2, *wk2, *wv2, *wo2;
    uint32_t *kx, *vf;
    cudaGetSymbolAddress((void**)&x4,    g_x4);
    cudaGetSymbolAddress((void**)&wq2,   g_wq2);
    cudaGetSymbolAddress((void**)&wk2,   g_wk2);
    cudaGetSymbolAddress((void**)&wv2,   g_wv2);
    cudaGetSymbolAddress((void**)&wo2,   g_wo2);
    cudaGetSymbolAddress((void**)&q4,    g_q4);
    cudaGetSymbolAddress((void**)&kx,    g_kx);
    cudaGetSymbolAddress((void**)&vf,    g_vf);
    cudaGetSymbolAddress((void**)&attn4, g_attn4);

    const int M = BB * TT;    // 4096
    const size_t gsmem = 65536;

    cudaFuncSetAttribute(gemm_kernel<0>, cudaFuncAttributeMaxDynamicSharedMemorySize, (int)gsmem);
    cudaFuncSetAttribute(gemm_kernel<1>, cudaFuncAttributeMaxDynamicSharedMemorySize, (int)gsmem);
    cudaFuncSetAttribute(gemm_kernel<3>, cudaFuncAttributeMaxDynamicSharedMemorySize, (int)gsmem);
    cudaFuncSetAttribute(gemm_kernel<4>, cudaFuncAttributeMaxDynamicSharedMemorySize, (int)gsmem);

    // prepasses: rope table + operand packing (tf32 rounding done here, once)
    rope_init_kernel<<<TT * 64 / 256, 256>>>();
    pack_x_kernel<<<BB * TT * EE / 4 / 256, 256>>>(x);
    pack_w_kernel<<<4 * HH * DD,  256>>>(wq, wq2, HH * DD,  11);
    pack_w_kernel<<<4 * HKV * DD, 256>>>(wk, wk2, HKV * DD, 10);
    pack_w_kernel<<<4 * HKV * DD, 256>>>(wv, wv2, HKV * DD, 10);
    pack_w_kernel<<<4 * EE,       256>>>(wo, wo2, EE,       11);

    // QKV projections with fused rope/split/pack epilogues
    gemm_kernel<1><<<dim3(HH*DD/128,  M/128), 256, gsmem>>>(x4, wq2, q4, M, HH*DD,  EE);
    gemm_kernel<3><<<dim3(HKV*DD/128, M/128), 256, gsmem>>>(x4, wk2, kx, M, HKV*DD, EE);
    gemm_kernel<4><<<dim3(HKV*DD/128, M/128), 256, gsmem>>>(x4, wv2, vf, M, HKV*DD, EE);

    // Flash attention (114 KB dynamic smem, Q in registers)
    {
        size_t smem = (16384 + 8192 + 4608) * sizeof(uint32_t);  // 116736 B
        cudaFuncSetAttribute(flash_kernel, cudaFuncAttributeMaxDynamicSharedMemorySize, (int)smem);
        flash_kernel<<<dim3(TT/QTILE, HH, BB), 256, smem>>>(q4, kx, vf, attn4);
    }

    // Output projection (packed attn, plain fp32 store)
    gemm_kernel<0><<<dim3(EE/128, M/128), 256, gsmem>>>(attn4, wo2, out, M, EE, EE);
}

// round 12
// speedup vs baseline: 9.4883x; 1.1387x over previous
#include <cuda_runtime.h>
#include <math.h>
#include <stdint.h>

#define BB 2
#define TT 2048
#define EE 2048
#define HH 16
#define HKV 8
#define DD 128
#define QTILE 128
#define KT32 32
#define NT32 (TT/KT32)      // 64 kv tiles
#define NCAT 4096           // fused QKV output columns
#define SCALE 0.08838834764831845f

// ---------------- scratch (static device globals; no allocation) ----------------
__device__ uint4    g_x4[BB*TT*EE/4];                 // packed-A x (tf32 bits)
__device__ uint2    g_wqkv2[EE/8*NCAT*4];             // packed-B wq|wk|wv (tf32 bits)
__device__ uint2    g_wo2[HH*DD/8*EE*4];              // packed-B wo
__device__ uint4    g_q4[BB*HH*TT*DD/4];              // packed-A Q (rope+scale, tf32)
__device__ uint32_t g_kx[BB*HKV*NT32*16*32*4*2];      // packed K (hi only): {h,h4}
__device__ uint32_t g_vf[BB*HKV*NT32*4*128*4*2];      // packed V: {v,v4}
__device__ uint4    g_attn4[BB*TT*HH*DD/4];           // packed-A attn (tf32)
__device__ float2   g_rope[TT*64];                    // per (t,j) {cos,sin}

__device__ __forceinline__ uint32_t f2tf(float x) {
    uint32_t u;
    asm("cvt.rna.tf32.f32 %0, %1;" : "=r"(u) : "f"(x));
    return u;
}

__device__ __forceinline__ void mma_tf32(float* d, const uint32_t* a, const uint32_t* b) {
    asm volatile(
        "mma.sync.aligned.m16n8k8.row.col.f32.tf32.tf32.f32 "
        "{%0,%1,%2,%3}, {%4,%5,%6,%7}, {%8,%9}, {%0,%1,%2,%3};"
        : "+f"(d[0]), "+f"(d[1]), "+f"(d[2]), "+f"(d[3])
        : "r"(a[0]), "r"(a[1]), "r"(a[2]), "r"(a[3]), "r"(b[0]), "r"(b[1]));
}

__device__ __forceinline__ void cp16(uint32_t saddr, const void* gptr) {
    asm volatile("cp.async.cg.shared.global [%0], [%1], 16;" :: "r"(saddr), "l"(gptr));
}

// ---------------- prepasses ----------------
__global__ void rope_init_kernel() {
    int i = blockIdx.x * 256 + threadIdx.x;     // < TT*64
    int j = i & 63, t = i >> 6;
    float inv = exp2f(-0.20762050593045952f * (float)j);  // 10000^(-j/64)
    float s, c;
    sincosf((float)t * inv, &s, &c);
    g_rope[i] = make_float2(c, s);
}

// x[4096][2048] -> packed-A uint4 fragments {(m,k),(m+8,k),(m,k+4),(m+8,k+4)}
__global__ void pack_x_kernel(const float* __restrict__ x) {
    int id = blockIdx.x * 256 + threadIdx.x;    // < 2097152
    int lc = id & 3, lr = (id >> 2) & 7, kg = (id >> 5) & 255, mb = id >> 13;
    const float* p = x + (size_t)(mb * 16 + lr) * 2048 + kg * 8 + lc;
    g_x4[id] = make_uint4(f2tf(p[0]), f2tf(p[8 * 2048]), f2tf(p[4]), f2tf(p[8 * 2048 + 4]));
}

// w[K=2048][Nsrc] -> packed-B uint2 {(k,n),(k+4,n)} at [(kg*Ntot + noff + n)*4 + lc]
__global__ void pack_w_kernel(const float* __restrict__ w, uint2* __restrict__ out,
                              int nsh, int Ntot, int noff) {
    int id = blockIdx.x * 256 + threadIdx.x;    // < 256 * Nsrc * 4
    int Nsrc = 1 << nsh;
    int lc = id & 3, n = (id >> 2) & (Nsrc - 1), kg = id >> (2 + nsh);
    const float* p = w + (size_t)(kg * 8 + lc) * Nsrc + n;
    out[((size_t)kg * Ntot + noff + n) * 4 + lc] = make_uint2(f2tf(p[0]), f2tf(p[4 * Nsrc]));
}

// ---------------- pipelined tf32 GEMM on pre-packed operands ----------------
// EPI: 0 plain fp32 store | 5 fused QKV epilogue (Q rope->g_q4, K rope->g_kx, V->g_vf)
template<int EPI>
__global__ __launch_bounds__(256, 2)
void gemm_kernel(const uint4* __restrict__ A4, const uint2* __restrict__ B2,
                 void* __restrict__ Cout, int M, int N, int K) {
    extern __shared__ uint32_t smu[];
    uint4* As4 = (uint4*)smu;                  // [2][1024] uint4 (16KB/stage)
    uint2* Bs2 = (uint2*)(smu + 2 * 1024 * 4); // [2][2048] uint2 (16KB/stage)

    const int tid  = threadIdx.x;
    const int brow = blockIdx.y * 128;
    const int bcol = blockIdx.x * 128;
    const int lane = tid & 31, warp = tid >> 5;
    const int wr = warp >> 2, wc = warp & 3;
    const int n_base = wc * 32;
    const int lr = lane >> 2, lc = lane & 3;
    const int KG = K >> 3;

    float acc[4][4][4];
#pragma unroll
    for (int mt = 0; mt < 4; mt++)
#pragma unroll
        for (int nt = 0; nt < 4; nt++)
#pragma unroll
            for (int i = 0; i < 4; i++) acc[mt][nt][i] = 0.f;

    const uint32_t as_base = (uint32_t)__cvta_generic_to_shared(As4);
    const uint32_t bs_base = (uint32_t)__cvta_generic_to_shared(Bs2);

#define LOAD_TILE(K0, BUF)                                                              \
    {                                                                                   \
        const int kg0 = (K0) >> 3;                                                      \
        _Pragma("unroll")                                                               \
        for (int i = 0; i < 4; i++) {                                                   \
            int id = tid + i * 256;                                                     \
            int mb = id >> 7, sub = id & 127;                                           \
            cp16(as_base + ((BUF) * 1024 + mb * 128 + sub) * 16,                        \
                 A4 + ((size_t)((brow >> 4) + mb) * KG + kg0 + (sub >> 5)) * 32         \
                    + (sub & 31));                                                      \
            int kgl = id >> 8, s2 = id & 255;                                           \
            int n = s2 >> 1, h2 = (id & 1) * 2;                                         \
            cp16(bs_base + ((BUF) * 2048 + (kgl * 128 + n) * 4 + h2) * 8,               \
                 B2 + ((size_t)(kg0 + kgl) * N + bcol + n) * 4 + h2);                   \
        }                                                                               \
        asm volatile("cp.async.commit_group;");                                         \
    }

    const int NIT = K >> 5;
    LOAD_TILE(0, 0);

    for (int it = 0; it < NIT; it++) {
        if (it + 1 < NIT) {
            LOAD_TILE((it + 1) << 5, (it + 1) & 1);
            asm volatile("cp.async.wait_group 1;");
        } else {
            asm volatile("cp.async.wait_group 0;");
        }
        __syncthreads();

        const uint4* Ab = As4 + (it & 1) * 1024;
        const uint2* Bb = Bs2 + (it & 1) * 2048;
#pragma unroll
        for (int ks = 0; ks < 4; ks++) {
            uint4 afr[4];
            uint2 bfr[4];
#pragma unroll
            for (int mt = 0; mt < 4; mt++)
                afr[mt] = Ab[(wr * 4 + mt) * 128 + ks * 32 + lane];
#pragma unroll
            for (int nt = 0; nt < 4; nt++)
                bfr[nt] = Bb[(ks * 128 + n_base + nt * 8 + lr) * 4 + lc];
#pragma unroll
            for (int mt = 0; mt < 4; mt++)
#pragma unroll
                for (int nt = 0; nt < 4; nt++)
                    mma_tf32(acc[mt][nt], (const uint32_t*)&afr[mt], (const uint32_t*)&bfr[nt]);
        }
        __syncthreads();
    }

    // ---------------- epilogue ----------------
#pragma unroll
    for (int mt = 0; mt < 4; mt++)
#pragma unroll
        for (int nt = 0; nt < 4; nt++) {
            int row = brow + wr * 64 + mt * 16 + lr;
            int col = bcol + n_base + nt * 8 + 2 * lc;
            float c0 = acc[mt][nt][0], c1 = acc[mt][nt][1];
            float c2 = acc[mt][nt][2], c3 = acc[mt][nt][3];
            if (EPI == 0) {
                float* C = (float*)Cout;
                *(float2*)(C + (size_t)row * N + col)       = make_float2(c0, c1);
                *(float2*)(C + (size_t)(row + 8) * N + col) = make_float2(c2, c3);
            } else {
                int b = row >> 11, t = row & (TT - 1);
                if (col < 2048) {
                    // Q: rope + scale -> packed-A fragment layout (g_q4)
                    int h = col >> 7, j = (col & 127) >> 1;
                    float2 r1 = g_rope[t * 64 + j];
                    float2 r2 = g_rope[(t + 8) * 64 + j];
                    float va = (c0 * r1.x - c1 * r1.y) * SCALE;
                    float vb = (c1 * r1.x + c0 * r1.y) * SCALE;
                    float vc = (c2 * r2.x - c3 * r2.y) * SCALE;
                    float vd = (c3 * r2.x + c2 * r2.y) * SCALE;
                    uint32_t* W = (uint32_t*)g_q4;
                    size_t bh = (size_t)(b * HH + h) * 65536;
                    int mblk = t >> 4, lrq = t & 7;
#pragma unroll
                    for (int e = 0; e < 2; e++) {
                        int d = (e == 0) ? j : j + 64;
                        float vh0 = (e == 0) ? va : vb;
                        float vh1 = (e == 0) ? vc : vd;
                        size_t u4 = bh + (size_t)(mblk * 16 + (d >> 3)) * 32 + lrq * 4 + ((d & 7) & 3);
                        uint32_t* p = W + u4 * 4 + (((d & 7) >> 2) << 1);
                        *(uint2*)p = make_uint2(f2tf(vh0), f2tf(vh1));
                    }
                } else if (col < 3072) {
                    // K: rope -> packed hi-only fragment layout (g_kx)
                    int colk = col - 2048;
                    int h = colk >> 7, j = (colk & 127) >> 1;
                    float2 r1 = g_rope[t * 64 + j];
                    float2 r2 = g_rope[(t + 8) * 64 + j];
                    float va = c0 * r1.x - c1 * r1.y;
                    float vb = c1 * r1.x + c0 * r1.y;
                    float vc = c2 * r2.x - c3 * r2.y;
                    float vd = c3 * r2.x + c2 * r2.y;
                    size_t bh = (size_t)(b * HKV + h) * NT32;
#pragma unroll
                    for (int e = 0; e < 4; e++) {
                        int tt = (e < 2) ? t : t + 8;
                        int d  = (e & 1) ? j + 64 : j;
                        float val = (e == 0) ? va : (e == 1) ? vb : (e == 2) ? vc : vd;
                        int tile = tt >> 5, r = tt & 31, kb = d >> 3, c = d & 7;
                        g_kx[(((bh + tile) * 16 + kb) * 32 + r) * 8 + (c & 3) * 2 + (c >> 2)] = f2tf(val);
                    }
                } else {
                    // V: packed fragment layout (g_vf)
                    int colv = col - 3072;
                    int h = colv >> 7, d = colv & 127;
                    size_t bh = (size_t)(b * HKV + h) * NT32;
#pragma unroll
                    for (int e = 0; e < 4; e++) {
                        int tt = (e < 2) ? t : t + 8;
                        int dd = d + (e & 1);
                        float val = (e == 0) ? c0 : (e == 1) ? c1 : (e == 2) ? c2 : c3;
                        int tile = tt >> 5, kb = (tt & 31) >> 3, lct = tt & 3, pi = (tt & 7) >> 2;
                        g_vf[(((bh + tile) * 4 + kb) * 128 + dd) * 8 + lct * 2 + pi] = f2tf(val);
                    }
                }
            }
        }
}

// ---------------- Tensor-core flash attention (tf32 mma, causal) ----------------
// grid: (T/128, H, B); 256 threads (8 warps), 2 CTAs/SM, heavy tiles first.
// Q streamed from L2 (packed fragments); K single tf32; PV single tf32; MUFU exp.
__global__ __launch_bounds__(256, 2)
void flash_kernel(const uint4* __restrict__ Q4, const uint32_t* __restrict__ KXg,
                  const uint32_t* __restrict__ VFg, uint4* __restrict__ Attn4) {
    extern __shared__ uint32_t smu[];
    uint32_t* KX = smu;                    // 2 x 4096  (packed K tile, hi only)
    uint32_t* VF = smu + 8192;             // 2 x 4096  (packed V tile)
    uint32_t* Ps = smu + 16384;            // 128 x 36  (tf32 P)

    const int tid = threadIdx.x;
    const int qt = gridDim.x - 1 - blockIdx.x;   // heavy (large-qt) blocks first
    const int h = blockIdx.y, b = blockIdx.z;
    const int q0 = qt * QTILE;
    const int hkv = h & (HKV - 1);
    const int warp = tid >> 5, lane = tid & 31;
    const int lr = lane >> 2, lc = lane & 3;
    const int m0 = warp * 16;
    const int ra = m0 + lr, rb = ra + 8;
    const int grow_a = q0 + ra, grow_b = q0 + rb;

    // g_q4 holds 65536 uint4 per (b,h): 128 m-blocks x 16 kb x 32 lanes
    const uint4*    Qb = Q4 + (size_t)(b * HH + h) * 65536 + (size_t)(qt * 8 + warp) * 512;
    const uint32_t* Kt = KXg + (size_t)(b * HKV + hkv) * NT32 * 4096;
    const uint32_t* Vt = VFg + (size_t)(b * HKV + hkv) * NT32 * 4096;

    const uint32_t kx_base = (uint32_t)__cvta_generic_to_shared(KX);
    const uint32_t vf_base = (uint32_t)__cvta_generic_to_shared(VF);

#define KV_ISSUE(KTT, BUF)                                                      \
    {                                                                           \
        _Pragma("unroll")                                                       \
        for (int i = 0; i < 4; i++) {                                           \
            int id = tid + i * 256;                                             \
            cp16(kx_base + ((BUF) * 4096 + id * 4) * 4,                         \
                 Kt + (size_t)(KTT) * 4096 + id * 4);                           \
            cp16(vf_base + ((BUF) * 4096 + id * 4) * 4,                         \
                 Vt + (size_t)(KTT) * 4096 + id * 4);                           \
        }                                                                       \
        asm volatile("cp.async.commit_group;");                                 \
    }

    const int nkt = 4 * (qt + 1);
    KV_ISSUE(0, 0);

    float O[16][4];
#pragma unroll
    for (int nb = 0; nb < 16; nb++)
#pragma unroll
        for (int i = 0; i < 4; i++) O[nb][i] = 0.f;
    float m_a = -1e30f, m_b = -1e30f, l_a = 0.f, l_b = 0.f;

    for (int kt = 0; kt < nkt; kt++) {
        asm volatile("cp.async.wait_group 0;");
        __syncthreads();
        if (kt + 1 < nkt) KV_ISSUE(kt + 1, (kt + 1) & 1);

        const uint2* Kb = (const uint2*)(KX + (kt & 1) * 4096);
        const uint32_t* Vb = VF + (kt & 1) * 4096;

        // ---- S = Q @ K^T (Q streamed from L2, single tf32 mma) ----
        float S[4][4];
#pragma unroll
        for (int nb = 0; nb < 4; nb++)
#pragma unroll
            for (int i = 0; i < 4; i++) S[nb][i] = 0.f;

#pragma unroll
        for (int ks = 0; ks < 16; ks++) {
            uint4 qf = Qb[ks * 32 + lane];
            uint2 kf[4];
#pragma unroll
            for (int nb = 0; nb < 4; nb++)
                kf[nb] = Kb[(ks * 32 + nb * 8 + lr) * 4 + lc];
#pragma unroll
            for (int nb = 0; nb < 4; nb++)
                mma_tf32(S[nb], (const uint32_t*)&qf, (const uint32_t*)&kf[nb]);
        }

        // ---- causal mask (only diagonal-overlapping tiles) ----
        const int s0 = kt * KT32;
        if (kt >= 4 * qt) {
#pragma unroll
            for (int nb = 0; nb < 4; nb++) {
                int col = s0 + nb * 8 + 2 * lc;
                if (col     > grow_a) S[nb][0] = -1e30f;
                if (col + 1 > grow_a) S[nb][1] = -1e30f;
                if (col     > grow_b) S[nb][2] = -1e30f;
                if (col + 1 > grow_b) S[nb][3] = -1e30f;
            }
        }

        // ---- online softmax (MUFU exp) ----
        float mxa = m_a, mxb = m_b;
#pragma unroll
        for (int nb = 0; nb < 4; nb++) {
            mxa = fmaxf(mxa, fmaxf(S[nb][0], S[nb][1]));
            mxb = fmaxf(mxb, fmaxf(S[nb][2], S[nb][3]));
        }
        mxa = fmaxf(mxa, __shfl_xor_sync(0xffffffffu, mxa, 1));
        mxa = fmaxf(mxa, __shfl_xor_sync(0xffffffffu, mxa, 2));
        mxb = fmaxf(mxb, __shfl_xor_sync(0xffffffffu, mxb, 1));
        mxb = fmaxf(mxb, __shfl_xor_sync(0xffffffffu, mxb, 2));

        float corr_a = __expf(m_a - mxa);
        float corr_b = __expf(m_b - mxb);
        m_a = mxa; m_b = mxb;

        float suma = 0.f, sumb = 0.f;
#pragma unroll
        for (int nb = 0; nb < 4; nb++) {
            float p0 = __expf(S[nb][0] - mxa);
            float p1 = __expf(S[nb][1] - mxa);
            float p2 = __expf(S[nb][2] - mxb);
            float p3 = __expf(S[nb][3] - mxb);
            suma += p0 + p1;
            sumb += p2 + p3;
            *(uint2*)(Ps + ra * 36 + nb * 8 + 2 * lc) = make_uint2(f2tf(p0), f2tf(p1));
            *(uint2*)(Ps + rb * 36 + nb * 8 + 2 * lc) = make_uint2(f2tf(p2), f2tf(p3));
        }
        suma += __shfl_xor_sync(0xffffffffu, suma, 1);
        suma += __shfl_xor_sync(0xffffffffu, suma, 2);
        sumb += __shfl_xor_sync(0xffffffffu, sumb, 1);
        sumb += __shfl_xor_sync(0xffffffffu, sumb, 2);
        l_a = l_a * corr_a + suma;
        l_b = l_b * corr_b + sumb;

#pragma unroll
        for (int nb = 0; nb < 16; nb++) {
            O[nb][0] *= corr_a; O[nb][1] *= corr_a;
            O[nb][2] *= corr_b; O[nb][3] *= corr_b;
        }
        __syncwarp();    // P is warp-private (rows of this warp only)

        // ---- O += P @ V ----
#pragma unroll
        for (int ks = 0; ks < 4; ks++) {
            const int k0 = ks * 8;
            uint32_t a[4] = { Ps[ra * 36 + k0 + lc],
                              Ps[rb * 36 + k0 + lc],
                              Ps[ra * 36 + k0 + lc + 4],
                              Ps[rb * 36 + k0 + lc + 4] };
#pragma unroll
            for (int nb = 0; nb < 16; nb++) {
                uint2 vv = *(const uint2*)(Vb + ((ks * 128 + nb * 8 + lr) * 4 + lc) * 2);
                mma_tf32(O[nb], a, (const uint32_t*)&vv);
            }
        }
    }

    // ---- epilogue: normalize + write packed-A attn (tf32 bits) ----
    float inva = 1.0f / l_a, invb = 1.0f / l_b;
    uint32_t* attnW = (uint32_t*)Attn4;
    const int mblk = b * 128 + qt * 8 + warp;
    const int lcp0 = (2 * lc) & 3, lcp1 = (2 * lc + 1) & 3;
    const int hi2  = ((2 * lc) >> 2) << 1;
#pragma unroll
    for (int nb = 0; nb < 16; nb++) {
        size_t sb = ((size_t)(mblk * 256 + h * 16 + nb) * 8 + lr) * 16;
        *(uint2*)(attnW + sb + lcp0 * 4 + hi2) =
            make_uint2(f2tf(O[nb][0] * inva), f2tf(O[nb][2] * invb));
        *(uint2*)(attnW + sb + lcp1 * 4 + hi2) =
            make_uint2(f2tf(O[nb][1] * inva), f2tf(O[nb][3] * invb));
    }
}

// ---------------- launch ----------------
extern "C" void kernel_launch(void* const* d_in, const int* in_sizes, int n_in,
                              void* d_out, int out_size) {
    const float* x  = (const float*)d_in[0];
    const float* wq = (const float*)d_in[2];
    const float* wk = (const float*)d_in[3];
    const float* wv = (const float*)d_in[4];
    const float* wo = (const float*)d_in[5];
    float* out = (float*)d_out;

    uint4 *x4, *q4, *attn4;
    uint2 *wqkv2, *wo2;
    uint32_t *kx, *vf;
    cudaGetSymbolAddress((void**)&x4,    g_x4);
    cudaGetSymbolAddress((void**)&wqkv2, g_wqkv2);
    cudaGetSymbolAddress((void**)&wo2,   g_wo2);
    cudaGetSymbolAddress((void**)&q4,    g_q4);
    cudaGetSymbolAddress((void**)&kx,    g_kx);
    cudaGetSymbolAddress((void**)&vf,    g_vf);
    cudaGetSymbolAddress((void**)&attn4, g_attn4);

    const int M = BB * TT;    // 4096
    const size_t gsmem = 65536;

    cudaFuncSetAttribute(gemm_kernel<0>, cudaFuncAttributeMaxDynamicSharedMemorySize, (int)gsmem);
    cudaFuncSetAttribute(gemm_kernel<5>, cudaFuncAttributeMaxDynamicSharedMemorySize, (int)gsmem);

    // prepasses: rope table + operand packing (tf32 rounding done once)
    rope_init_kernel<<<TT * 64 / 256, 256>>>();
    pack_x_kernel<<<BB * TT * EE / 4 / 256, 256>>>(x);
    pack_w_kernel<<<4 * 2048, 256>>>(wq, wqkv2, 11, NCAT, 0);
    pack_w_kernel<<<4 * 1024, 256>>>(wk, wqkv2, 10, NCAT, 2048);
    pack_w_kernel<<<4 * 1024, 256>>>(wv, wqkv2, 10, NCAT, 3072);
    pack_w_kernel<<<4 * 2048, 256>>>(wo, wo2, 11, EE, 0);

    // Fused QKV projection (one launch, epilogue dispatched by column block)
    gemm_kernel<5><<<dim3(NCAT/128, M/128), 256, gsmem>>>(x4, wqkv2, nullptr, M, NCAT, EE);

    // Flash attention (82 KB dynamic smem, 2 CTAs/SM)
    {
        size_t smem = (8192 + 8192 + 4608) * sizeof(uint32_t);  // 83968 B
        cudaFuncSetAttribute(flash_kernel, cudaFuncAttributeMaxDynamicSharedMemorySize, (int)smem);
        flash_kernel<<<dim3(TT/QTILE, HH, BB), 256, smem>>>(q4, kx, vf, attn4);
    }

    // Output projection (packed attn, plain fp32 store)
    gemm_kernel<0><<<dim3(EE/128, M/128), 256, gsmem>>>(attn4, wo2, out, M, EE, EE);
}